// round 8
// baseline (speedup 1.0000x reference)
#include <cuda_runtime.h>
#include <cuda_bf16.h>
#include <math.h>

// ---------------------------------------------------------------------------
// Struct2SeqGCN: CGConv x4 + BN + LN blocks + final LN + FC
// N=20000 nodes, E=320000 edges, H=128, 4 layers, 16 RBF gaussians
// ---------------------------------------------------------------------------

#define NMAX   20000
#define EMAX   320000
#define HID    128
#define NBINS  2048            // lerp table bins (rows = NBINS+1)
#define NPART  157             // ceil(20000/128)

// ------------------------- static scratch (no allocs) ----------------------
__device__ __align__(16) float g_h   [NMAX * HID];        // node features
__device__ __align__(16) float g_AB  [NMAX * 4 * HID];    // [Af | Bf | As | Bs]
__device__ __align__(16) float g_agg [NMAX * HID];        // aggregated messages
__device__ __align__(16) float g_Tf  [(NBINS + 1) * HID]; // lerp table (f gate)
__device__ __align__(16) float g_Ts  [(NBINS + 1) * HID]; // lerp table (s gate)
__device__ int   g_degcur[2 * NMAX];                      // [deg | cur], one zeroing
__device__ int   g_rowptr[NMAX + 1];
__device__ int   g_csrc[EMAX];
__device__ float g_cpos[EMAX];
__device__ __align__(16) float g_part[NPART * 2 * HID];   // BN partials
__device__ __align__(16) float g_bns [2 * HID];           // BN fused scale/shift

// ------------------------------ helpers ------------------------------------
__device__ __forceinline__ float fsigmoid(float x) {
    return __fdividef(1.0f, 1.0f + __expf(-x));
}
__device__ __forceinline__ float fsoftplus(float x) {
    return fmaxf(x, 0.0f) + __logf(1.0f + __expf(-fabsf(x)));
}

// ------------------------------ CSR build ----------------------------------
__global__ void zero_kernel(int* a, int n) {
    int i = blockIdx.x * blockDim.x + threadIdx.x;
    if (i < n) a[i] = 0;
}

__global__ void hist_kernel(const int* __restrict__ ei, int* __restrict__ deg, int E) {
    int e = blockIdx.x * blockDim.x + threadIdx.x;
    if (e < E) atomicAdd(&deg[ei[E + e]], 1);   // row 1 = dst
}

__global__ void scan_kernel(const int* __restrict__ deg, int* __restrict__ rowptr, int n) {
    __shared__ int wsum[32];
    __shared__ int carry;
    if (threadIdx.x == 0) carry = 0;
    __syncthreads();
    int lane = threadIdx.x & 31, wid = threadIdx.x >> 5;
    for (int base = 0; base < n; base += 1024) {
        int i = base + (int)threadIdx.x;
        int v = (i < n) ? deg[i] : 0;
        int x = v;
        #pragma unroll
        for (int d = 1; d < 32; d <<= 1) {
            int y = __shfl_up_sync(0xffffffffu, x, d);
            if (lane >= d) x += y;
        }
        if (lane == 31) wsum[wid] = x;
        __syncthreads();
        if (wid == 0) {
            int s = wsum[lane];
            #pragma unroll
            for (int d = 1; d < 32; d <<= 1) {
                int y = __shfl_up_sync(0xffffffffu, s, d);
                if (lane >= d) s += y;
            }
            wsum[lane] = s;
        }
        __syncthreads();
        int pre  = (wid > 0) ? wsum[wid - 1] : 0;
        int incl = x + pre;
        int c0   = carry;
        if (i < n) rowptr[i] = c0 + incl - v;   // exclusive
        __syncthreads();
        if (threadIdx.x == 1023) carry = c0 + incl;
        __syncthreads();
    }
    if (threadIdx.x == 0) rowptr[n] = carry;
}

__global__ void scatter_kernel(const int* __restrict__ ei, const float* __restrict__ dist,
                               const int* __restrict__ rowptr, int* __restrict__ cur,
                               int* __restrict__ csrc, float* __restrict__ cpos, int E) {
    int e = blockIdx.x * blockDim.x + threadIdx.x;
    if (e >= E) return;
    int s = ei[e];
    int d = ei[E + e];
    int pos = rowptr[d] + atomicAdd(&cur[d], 1);
    csrc[pos] = s;
    float p = dist[e] * ((float)NBINS / 8.0f);
    cpos[pos] = fminf(fmaxf(p, 0.0f), (float)NBINS - 0.001f);
}

// --------------------------- node embedding --------------------------------
__global__ void embed_kernel(const float* __restrict__ x, const float* __restrict__ W,
                             const float* __restrict__ b, float* __restrict__ h, int N) {
    int i = blockIdx.x * blockDim.x + threadIdx.x;
    if (i >= N * HID) return;
    int n = i >> 7, c = i & 127;
    float acc = b[c];
    #pragma unroll
    for (int k = 0; k < 6; k++) acc += x[n * 6 + k] * W[k * HID + c];
    h[i] = acc;
}

// ----------------------- edge RBF lerp table build -------------------------
__global__ void table_kernel(const float* __restrict__ Wfe, const float* __restrict__ bf,
                             const float* __restrict__ Wse, const float* __restrict__ bs,
                             float* __restrict__ Tf, float* __restrict__ Ts) {
    int b = blockIdx.x;          // 0..NBINS
    int c = threadIdx.x;         // 0..127
    float d = (float)b * (8.0f / (float)NBINS);
    float af = bf[c], as = bs[c];
    #pragma unroll
    for (int g = 0; g < 16; g++) {
        float off = (float)g * (8.0f / 15.0f);
        float t = d - off;
        float e = expf(-1.7578125f * t * t);   // COEFF = -0.5/(8/15)^2
        af += e * Wfe[g * HID + c];
        as += e * Wse[g * HID + c];
    }
    Tf[b * HID + c] = af;
    Ts[b * HID + c] = as;
}

// ------------------ node precompute GEMM: h[Nx128] @ W[128x512] ------------
// Double-buffered smem, one __syncthreads per k-tile.
// C layout per node row: [Af | Bf | As | Bs] (512 floats)
__global__ __launch_bounds__(256)
void sgemm_kernel(const float* __restrict__ A, const float* __restrict__ Wfl,
                  const float* __restrict__ Wsl, float* __restrict__ C, int M) {
    __shared__ float As_[2][16][132];
    __shared__ float Bs_[2][16][128];
    int part = blockIdx.y;
    const float* Bpart = ((part < 2) ? Wfl : Wsl) + (part & 1) * (HID * HID);
    int m0  = blockIdx.x * 128;
    int tid = threadIdx.x;
    int tm = tid >> 4, tn = tid & 15;
    float acc[8][8] = {};

    int r  = tid >> 2;
    int kq = (tid & 3) * 4;
    int kk = tid >> 5;
    int j  = (tid & 31) * 4;

    // prologue: tile 0 -> buffer 0
    #pragma unroll
    for (int rr = 0; rr < 2; rr++) {
        int row = r + rr * 64;
        int gm  = m0 + row;
        float4 v = (gm < M) ? *(const float4*)(A + (size_t)gm * HID + kq)
                            : make_float4(0.f, 0.f, 0.f, 0.f);
        As_[0][kq + 0][row] = v.x; As_[0][kq + 1][row] = v.y;
        As_[0][kq + 2][row] = v.z; As_[0][kq + 3][row] = v.w;
        float4 w = *(const float4*)(Bpart + (size_t)(kk + rr * 8) * HID + j);
        *(float4*)&Bs_[0][kk + rr * 8][j] = w;
    }
    __syncthreads();

    #pragma unroll
    for (int kt = 0; kt < 8; kt++) {
        int cur = kt & 1, nxt = cur ^ 1;
        float4 va[2], vb[2];
        if (kt < 7) {
            int k0 = (kt + 1) * 16;
            #pragma unroll
            for (int rr = 0; rr < 2; rr++) {
                int gm = m0 + r + rr * 64;
                va[rr] = (gm < M) ? *(const float4*)(A + (size_t)gm * HID + k0 + kq)
                                  : make_float4(0.f, 0.f, 0.f, 0.f);
                vb[rr] = *(const float4*)(Bpart + (size_t)(k0 + kk + rr * 8) * HID + j);
            }
        }
        #pragma unroll
        for (int kki = 0; kki < 16; kki++) {
            float a[8], bb[8];
            *(float4*)&a[0]  = *(float4*)&As_[cur][kki][tm * 8];
            *(float4*)&a[4]  = *(float4*)&As_[cur][kki][tm * 8 + 4];
            *(float4*)&bb[0] = *(float4*)&Bs_[cur][kki][tn * 8];
            *(float4*)&bb[4] = *(float4*)&Bs_[cur][kki][tn * 8 + 4];
            #pragma unroll
            for (int i = 0; i < 8; i++)
                #pragma unroll
                for (int jj = 0; jj < 8; jj++)
                    acc[i][jj] += a[i] * bb[jj];
        }
        if (kt < 7) {
            #pragma unroll
            for (int rr = 0; rr < 2; rr++) {
                int row = r + rr * 64;
                As_[nxt][kq + 0][row] = va[rr].x; As_[nxt][kq + 1][row] = va[rr].y;
                As_[nxt][kq + 2][row] = va[rr].z; As_[nxt][kq + 3][row] = va[rr].w;
                *(float4*)&Bs_[nxt][kk + rr * 8][j] = vb[rr];
            }
            __syncthreads();
        }
    }
    #pragma unroll
    for (int i = 0; i < 8; i++) {
        int gm = m0 + tm * 8 + i;
        if (gm < M) {
            float* cp = C + (size_t)gm * 512 + part * 128 + tn * 8;
            *(float4*)cp       = make_float4(acc[i][0], acc[i][1], acc[i][2], acc[i][3]);
            *(float4*)(cp + 4) = make_float4(acc[i][4], acc[i][5], acc[i][6], acc[i][7]);
        }
    }
}

// --------------------- edge message + aggregation (CSR) --------------------
// Warp per dst node; 2-stage software pipeline: next edge's 6 gathers are in
// flight while the current edge's sigmoid/softplus math executes.
__global__ __launch_bounds__(128)
void agg_kernel(const float* __restrict__ AB, const int* __restrict__ rowptr,
                const int* __restrict__ csrc, const float* __restrict__ cpos,
                const float* __restrict__ Tfp, const float* __restrict__ Tsp,
                float* __restrict__ agg, int N) {
    int node = (blockIdx.x * blockDim.x + threadIdx.x) >> 5;
    if (node >= N) return;
    int lane = threadIdx.x & 31;
    const float4* ABv = (const float4*)AB;   // 128 float4 per node row
    const float4* Tf4 = (const float4*)Tfp;  // 32 float4 per bin row
    const float4* Ts4 = (const float4*)Tsp;

    float4 af  = ABv[(size_t)node * 128 + lane];        // Af: floats [0,128)
    float4 as_ = ABv[(size_t)node * 128 + 64 + lane];   // As: floats [256,384)
    float4 acc = make_float4(0.f, 0.f, 0.f, 0.f);

    int beg = rowptr[node], end = rowptr[node + 1];
    if (beg < end) {
        // prologue: fetch edge 'beg'
        int   s = csrc[beg];
        float p = cpos[beg];
        int   k = (int)p;
        float t = p - (float)k;
        float4 bf = ABv[(size_t)s * 128 + 32 + lane];
        float4 bs = ABv[(size_t)s * 128 + 96 + lane];
        float4 f0 = Tf4[(size_t)k * 32 + lane];
        float4 f1 = Tf4[(size_t)(k + 1) * 32 + lane];
        float4 s0 = Ts4[(size_t)k * 32 + lane];
        float4 s1 = Ts4[(size_t)(k + 1) * 32 + lane];

        #pragma unroll 2
        for (int i = beg; i < end; i++) {
            // stage current edge
            float  tc  = t;
            float4 cbf = bf, cbs = bs, cf0 = f0, cf1 = f1, cs0 = s0, cs1 = s1;
            // prefetch next edge (issues loads before the MUFU-heavy math)
            if (i + 1 < end) {
                int   sn = csrc[i + 1];
                float pn = cpos[i + 1];
                int   kn = (int)pn;
                t  = pn - (float)kn;
                bf = ABv[(size_t)sn * 128 + 32 + lane];
                bs = ABv[(size_t)sn * 128 + 96 + lane];
                f0 = Tf4[(size_t)kn * 32 + lane];
                f1 = Tf4[(size_t)(kn + 1) * 32 + lane];
                s0 = Ts4[(size_t)kn * 32 + lane];
                s1 = Ts4[(size_t)(kn + 1) * 32 + lane];
            }
            // compute current edge
            float fx = af.x + cbf.x + cf0.x + tc * (cf1.x - cf0.x);
            float fy = af.y + cbf.y + cf0.y + tc * (cf1.y - cf0.y);
            float fz = af.z + cbf.z + cf0.z + tc * (cf1.z - cf0.z);
            float fw = af.w + cbf.w + cf0.w + tc * (cf1.w - cf0.w);
            float sx = as_.x + cbs.x + cs0.x + tc * (cs1.x - cs0.x);
            float sy = as_.y + cbs.y + cs0.y + tc * (cs1.y - cs0.y);
            float sz = as_.z + cbs.z + cs0.z + tc * (cs1.z - cs0.z);
            float sw = as_.w + cbs.w + cs0.w + tc * (cs1.w - cs0.w);

            acc.x += fsigmoid(fx) * fsoftplus(sx);
            acc.y += fsigmoid(fy) * fsoftplus(sy);
            acc.z += fsigmoid(fz) * fsoftplus(sz);
            acc.w += fsigmoid(fw) * fsoftplus(sw);
        }
    }
    ((float4*)agg)[(size_t)node * 32 + lane] = acc;
}

// --------------------------- BatchNorm stats -------------------------------
__global__ void bn_part_kernel(const float* __restrict__ agg, float* __restrict__ part, int N) {
    int c = threadIdx.x;            // 128
    int b = blockIdx.x;             // NPART
    int r0 = b * 128, r1 = min(r0 + 128, N);
    float s = 0.f, q = 0.f;
    for (int r = r0; r < r1; r++) {
        float v = agg[(size_t)r * HID + c];
        s += v; q += v * v;
    }
    part[b * 256 + c]       = s;
    part[b * 256 + 128 + c] = q;
}

__global__ void bn_fin_kernel(const float* __restrict__ part, const float* __restrict__ g,
                              const float* __restrict__ b, float* __restrict__ sb,
                              int nb, int N) {
    int c = threadIdx.x;
    float s = 0.f, q = 0.f;
    for (int i = 0; i < nb; i++) {
        s += part[i * 256 + c];
        q += part[i * 256 + 128 + c];
    }
    float invN = 1.0f / (float)N;
    float mu  = s * invN;
    float var = fmaxf(q * invN - mu * mu, 0.0f);
    float sc  = g[c] * rsqrtf(var + 1e-5f);
    sb[c]       = sc;
    sb[128 + c] = b[c] - mu * sc;
}

// ---------------- BN-apply + residual + LayerNorm + ReLU + residual --------
__global__ __launch_bounds__(128)
void update_kernel(float* __restrict__ h, const float* __restrict__ agg,
                   const float* __restrict__ sb, const float* __restrict__ lng,
                   const float* __restrict__ lnb, int N) {
    int node = (blockIdx.x * blockDim.x + threadIdx.x) >> 5;
    if (node >= N) return;
    int lane = threadIdx.x & 31;
    float4 a  = ((const float4*)agg)[(size_t)node * 32 + lane];
    float4 hv = ((const float4*)h)  [(size_t)node * 32 + lane];
    float4 sc = ((const float4*)sb)[lane];
    float4 sh = ((const float4*)sb)[32 + lane];

    float cx = a.x * sc.x + sh.x + hv.x;
    float cy = a.y * sc.y + sh.y + hv.y;
    float cz = a.z * sc.z + sh.z + hv.z;
    float cw = a.w * sc.w + sh.w + hv.w;

    float sum = cx + cy + cz + cw;
    #pragma unroll
    for (int d = 16; d; d >>= 1) sum += __shfl_xor_sync(0xffffffffu, sum, d);
    float m = sum * (1.0f / 128.0f);

    float dx = cx - m, dy = cy - m, dz = cz - m, dw = cw - m;
    float q = dx * dx + dy * dy + dz * dz + dw * dw;
    #pragma unroll
    for (int d = 16; d; d >>= 1) q += __shfl_xor_sync(0xffffffffu, q, d);
    float r = rsqrtf(q * (1.0f / 128.0f) + 1e-5f);

    float4 g4 = ((const float4*)lng)[lane];
    float4 b4 = ((const float4*)lnb)[lane];
    float4 o;
    o.x = fmaxf(dx * r * g4.x + b4.x, 0.f) + hv.x;
    o.y = fmaxf(dy * r * g4.y + b4.y, 0.f) + hv.y;
    o.z = fmaxf(dz * r * g4.z + b4.z, 0.f) + hv.z;
    o.w = fmaxf(dw * r * g4.w + b4.w, 0.f) + hv.w;
    ((float4*)h)[(size_t)node * 32 + lane] = o;
}

// ----------------------- final LayerNorm + FC ------------------------------
__global__ __launch_bounds__(128)
void out_kernel(const float* __restrict__ h, const float* __restrict__ g,
                const float* __restrict__ b, const float* __restrict__ Wfc,
                const float* __restrict__ bfc, float* __restrict__ out, int N) {
    __shared__ float sh[128];
    __shared__ float red[4];
    int n = blockIdx.x, c = threadIdx.x;
    int wid = c >> 5, lane = c & 31;
    float v = h[(size_t)n * HID + c];

    float s = v;
    #pragma unroll
    for (int d = 16; d; d >>= 1) s += __shfl_xor_sync(0xffffffffu, s, d);
    if (lane == 0) red[wid] = s;
    __syncthreads();
    float m = (red[0] + red[1] + red[2] + red[3]) * (1.0f / 128.0f);
    __syncthreads();

    float dv = v - m;
    float q = dv * dv;
    #pragma unroll
    for (int d = 16; d; d >>= 1) q += __shfl_xor_sync(0xffffffffu, q, d);
    if (lane == 0) red[wid] = q;
    __syncthreads();
    float var = (red[0] + red[1] + red[2] + red[3]) * (1.0f / 128.0f);

    float hn = dv * rsqrtf(var + 1e-5f) * g[c] + b[c];
    sh[c] = hn;
    __syncthreads();

    if (c < 21) {
        float acc = bfc[c];
        #pragma unroll 4
        for (int k = 0; k < 128; k++) acc += sh[k] * Wfc[k * 21 + c];
        out[(size_t)n * 21 + c] = acc;
    }
}

// ------------------------------- launch ------------------------------------
extern "C" void kernel_launch(void* const* d_in, const int* in_sizes, int n_in,
                              void* d_out, int out_size) {
    const float* x     = (const float*)d_in[0];
    const int*   ei    = (const int*)  d_in[1];
    const float* dist  = (const float*)d_in[2];
    const float* Wn    = (const float*)d_in[3];
    const float* bn    = (const float*)d_in[4];
    const float* Wf    = (const float*)d_in[5];
    const float* bf    = (const float*)d_in[6];
    const float* Ws    = (const float*)d_in[7];
    const float* bs    = (const float*)d_in[8];
    const float* bng   = (const float*)d_in[9];
    const float* bnb   = (const float*)d_in[10];
    const float* lng   = (const float*)d_in[11];
    const float* lnb   = (const float*)d_in[12];
    const float* lnog  = (const float*)d_in[13];
    const float* lnob  = (const float*)d_in[14];
    const float* Wfc   = (const float*)d_in[15];
    const float* bfc   = (const float*)d_in[16];

    const int N = in_sizes[0] / 6;        // 20000
    const int E = in_sizes[2];            // 320000
    const int L = in_sizes[6] / HID;      // 4
    const int Z = 2 * HID + 16;           // 272

    float* h      = g_h;
    float* AB     = g_AB;
    float* agg    = g_agg;
    int*   deg    = g_degcur;             // [0, N)
    int*   cur    = g_degcur + NMAX;      // [NMAX, NMAX+N)
    int*   rowptr = g_rowptr;

    // --- CSR build (once; edge_index is layer-invariant) ---
    zero_kernel<<<(2 * NMAX + 255) / 256, 256>>>(g_degcur, 2 * NMAX);
    hist_kernel<<<(E + 255) / 256, 256>>>(ei, deg, E);
    scan_kernel<<<1, 1024>>>(deg, rowptr, N);
    scatter_kernel<<<(E + 255) / 256, 256>>>(ei, dist, rowptr, cur, g_csrc, g_cpos, E);

    // --- initial node embedding ---
    embed_kernel<<<(N * HID + 255) / 256, 256>>>(x, Wn, bn, h, N);

    const int mtiles  = (N + 127) / 128;
    const int wblocks = (N * 32 + 127) / 128;   // 128-thread blocks, warp/node

    for (int l = 0; l < L; l++) {
        const float* Wfl = Wf + (size_t)l * Z * HID;
        const float* Wsl = Ws + (size_t)l * Z * HID;
        // node precompute [Af|Bf|As|Bs]
        sgemm_kernel<<<dim3(mtiles, 4), 256>>>(h, Wfl, Wsl, AB, N);
        // edge-term lerp tables (bias folded in)
        table_kernel<<<NBINS + 1, HID>>>(Wfl + 256 * HID, bf + l * HID,
                                         Wsl + 256 * HID, bs + l * HID, g_Tf, g_Ts);
        // gated message + segment-sum (pipelined gathers)
        agg_kernel<<<wblocks, 128>>>(AB, rowptr, g_csrc, g_cpos, g_Tf, g_Ts, agg, N);
        // BatchNorm over nodes
        bn_part_kernel<<<(N + 127) / 128, HID>>>(agg, g_part, N);
        bn_fin_kernel<<<1, HID>>>(g_part, bng + l * HID, bnb + l * HID,
                                  g_bns, (N + 127) / 128, N);
        // residual + LN + ReLU + residual
        update_kernel<<<wblocks, 128>>>(h, agg, g_bns, lng + l * HID, lnb + l * HID, N);
    }

    // final LN + FC
    out_kernel<<<N, HID>>>(h, lnog, lnob, Wfc, bfc, (float*)d_out, N);
}

// round 10
// speedup vs baseline: 23.3996x; 23.3996x over previous
#include <cuda_runtime.h>
#include <cuda_bf16.h>
#include <math.h>

// ---------------------------------------------------------------------------
// Struct2SeqGCN as ONE persistent kernel (grid-wide barriers between phases).
// N=20000 nodes, E=320000 edges, H=128, 4 layers, 16 RBF gaussians.
// ---------------------------------------------------------------------------

#define NMAX     20000
#define EMAX     320000
#define HID      128
#define NBINS    2048
#define LMAX     4
#define NBLOCKS  296            // 2 blocks per SM on 148 SMs (GB300 has 152)
#define NTHREADS 256

// ------------------------- static scratch (no allocs) ----------------------
__device__ __align__(16) float g_h   [NMAX * HID];
__device__ __align__(16) float g_AB  [NMAX * 4 * HID];           // [Af|Bf|As|Bs]
__device__ __align__(16) float g_agg [NMAX * HID];
__device__ __align__(16) float g_Tf  [LMAX * (NBINS + 1) * HID]; // all layers
__device__ __align__(16) float g_Ts  [LMAX * (NBINS + 1) * HID];
__device__ int   g_degcur[2 * NMAX];
__device__ int   g_rowptr[NMAX + 1];
__device__ int   g_csrc[EMAX];
__device__ float g_cpos[EMAX];
__device__ __align__(16) float g_part[NBLOCKS * 2 * HID];
__device__ __align__(16) float g_bns [2 * HID];

// grid barrier state (zero-initialized at module load; gen is monotonic)
__device__ volatile unsigned g_bar_gen;
__device__ unsigned          g_bar_cnt;

__device__ __forceinline__ void grid_sync() {
    __syncthreads();
    if (threadIdx.x == 0) {
        __threadfence();
        unsigned gen = g_bar_gen;
        if (atomicAdd(&g_bar_cnt, 1u) == NBLOCKS - 1) {
            g_bar_cnt = 0;
            __threadfence();
            g_bar_gen = gen + 1;
        } else {
            while (g_bar_gen == gen) { __nanosleep(64); }
        }
        __threadfence();
    }
    __syncthreads();
}

__device__ __forceinline__ float fsigmoid(float x) {
    return __fdividef(1.0f, 1.0f + __expf(-x));
}
__device__ __forceinline__ float fsoftplus(float x) {
    return fmaxf(x, 0.0f) + __logf(1.0f + __expf(-fabsf(x)));
}

// ---------------------------------------------------------------------------
__global__ __launch_bounds__(NTHREADS, 2)
void mega_kernel(const float* __restrict__ x, const int* __restrict__ ei,
                 const float* __restrict__ dist,
                 const float* __restrict__ Wn, const float* __restrict__ bnode,
                 const float* __restrict__ Wf, const float* __restrict__ bfp,
                 const float* __restrict__ Ws, const float* __restrict__ bsp,
                 const float* __restrict__ bng, const float* __restrict__ bnb,
                 const float* __restrict__ lng, const float* __restrict__ lnb,
                 const float* __restrict__ lnog, const float* __restrict__ lnob,
                 const float* __restrict__ Wfc, const float* __restrict__ bfc,
                 float* __restrict__ out, int N, int E, int L)
{
    __shared__ __align__(16) float sA[2][16][132];   // gemm A tiles (also Wfc cache)
    __shared__ __align__(16) float sB[2][16][128];   // gemm B tiles
    __shared__ __align__(16) float sBN[8][256];      // per-warp BN partials

    const int tid   = threadIdx.x;
    const int gtid  = blockIdx.x * NTHREADS + tid;
    const int nth   = NBLOCKS * NTHREADS;
    const int lane  = tid & 31;
    const int wid   = tid >> 5;
    const int gwarp = blockIdx.x * (NTHREADS / 32) + wid;
    const int nwarp = NBLOCKS * (NTHREADS / 32);
    const int Z     = 2 * HID + 16;                  // 272

    // ================= P0: zero degcur, embed, all-layer tables =============
    for (int i = gtid; i < 2 * NMAX; i += nth) g_degcur[i] = 0;

    for (int i = gtid; i < N * HID; i += nth) {
        int n = i >> 7, c = i & 127;
        float acc = bnode[c];
        #pragma unroll
        for (int k = 0; k < 6; k++) acc += x[n * 6 + k] * Wn[k * HID + c];
        g_h[i] = acc;
    }

    for (int i = gtid; i < L * (NBINS + 1) * HID; i += nth) {
        int l   = i / ((NBINS + 1) * HID);
        int rem = i - l * ((NBINS + 1) * HID);
        int b = rem >> 7, c = rem & 127;
        const float* Wfe = Wf + (size_t)l * Z * HID + 256 * HID;
        const float* Wse = Ws + (size_t)l * Z * HID + 256 * HID;
        float d  = (float)b * (8.0f / (float)NBINS);
        float af = bfp[l * HID + c], as = bsp[l * HID + c];
        #pragma unroll
        for (int g = 0; g < 16; g++) {
            float off = (float)g * (8.0f / 15.0f);
            float t = d - off;
            float e = expf(-1.7578125f * t * t);   // COEFF = -0.5/(8/15)^2
            af += e * Wfe[g * HID + c];
            as += e * Wse[g * HID + c];
        }
        g_Tf[i] = af;
        g_Ts[i] = as;
    }
    grid_sync();

    // ================= P1: degree histogram =================================
    for (int e = gtid; e < E; e += nth) atomicAdd(&g_degcur[ei[E + e]], 1);
    grid_sync();

    // ================= P2: exclusive scan (block 0, warp 0) =================
    if (blockIdx.x == 0 && wid == 0) {
        int carry = 0;
        for (int base = 0; base < N; base += 32) {
            int i = base + lane;
            int v = (i < N) ? g_degcur[i] : 0;
            int xs = v;
            #pragma unroll
            for (int d = 1; d < 32; d <<= 1) {
                int y = __shfl_up_sync(0xffffffffu, xs, d);
                if (lane >= d) xs += y;
            }
            if (i < N) g_rowptr[i] = carry + xs - v;
            carry += __shfl_sync(0xffffffffu, xs, 31);
        }
        if (lane == 0) g_rowptr[N] = carry;
    }
    grid_sync();

    // ================= P3: scatter edges into CSR ===========================
    for (int e = gtid; e < E; e += nth) {
        int s = ei[e];
        int d = ei[E + e];
        int pos = g_rowptr[d] + atomicAdd(&g_degcur[NMAX + d], 1);
        g_csrc[pos] = s;
        float p = dist[e] * ((float)NBINS / 8.0f);
        g_cpos[pos] = fminf(fmaxf(p, 0.0f), (float)NBINS - 0.001f);
    }
    grid_sync();

    const int mtiles = (N + 127) / 128;

    // ========================== layer loop ==================================
    for (int l = 0; l < L; l++) {
        const float* Wfl = Wf + (size_t)l * Z * HID;
        const float* Wsl = Ws + (size_t)l * Z * HID;

        // ---- P4: node precompute GEMM  h[Nx128] @ W[128x512] -> g_AB ----
        for (int job = blockIdx.x; job < 4 * mtiles; job += NBLOCKS) {
            __syncthreads();                 // protect smem reuse across jobs
            int part = job / mtiles;         // 0..3
            int m0   = (job - part * mtiles) * 128;
            const float* Bp = ((part < 2) ? Wfl : Wsl) + (part & 1) * (HID * HID);

            int tm = tid >> 4, tn = tid & 15;
            float acc[8][8] = {};
            int r   = tid >> 2;
            int kq  = (tid & 3) * 4;
            int kk2 = tid >> 5;
            int jj2 = (tid & 31) * 4;

            // prologue: k-tile 0 -> buffer 0
            #pragma unroll
            for (int rr = 0; rr < 2; rr++) {
                int row = r + rr * 64;
                int gm  = m0 + row;
                float4 v = (gm < N) ? *(const float4*)(g_h + (size_t)gm * HID + kq)
                                    : make_float4(0.f, 0.f, 0.f, 0.f);
                sA[0][kq + 0][row] = v.x; sA[0][kq + 1][row] = v.y;
                sA[0][kq + 2][row] = v.z; sA[0][kq + 3][row] = v.w;
                float4 w = *(const float4*)(Bp + (size_t)(kk2 + rr * 8) * HID + jj2);
                *(float4*)&sB[0][kk2 + rr * 8][jj2] = w;
            }
            __syncthreads();

            #pragma unroll
            for (int kt = 0; kt < 8; kt++) {
                int cur = kt & 1, nxt = cur ^ 1;
                float4 va[2], vb[2];
                if (kt < 7) {
                    int k0 = (kt + 1) * 16;
                    #pragma unroll
                    for (int rr = 0; rr < 2; rr++) {
                        int gm = m0 + r + rr * 64;
                        va[rr] = (gm < N) ? *(const float4*)(g_h + (size_t)gm * HID + k0 + kq)
                                          : make_float4(0.f, 0.f, 0.f, 0.f);
                        vb[rr] = *(const float4*)(Bp + (size_t)(k0 + kk2 + rr * 8) * HID + jj2);
                    }
                }
                #pragma unroll
                for (int kki = 0; kki < 16; kki++) {
                    float a[8], bb[8];
                    *(float4*)&a[0]  = *(float4*)&sA[cur][kki][tm * 8];
                    *(float4*)&a[4]  = *(float4*)&sA[cur][kki][tm * 8 + 4];
                    *(float4*)&bb[0] = *(float4*)&sB[cur][kki][tn * 8];
                    *(float4*)&bb[4] = *(float4*)&sB[cur][kki][tn * 8 + 4];
                    #pragma unroll
                    for (int i = 0; i < 8; i++)
                        #pragma unroll
                        for (int jj = 0; jj < 8; jj++)
                            acc[i][jj] += a[i] * bb[jj];
                }
                if (kt < 7) {
                    #pragma unroll
                    for (int rr = 0; rr < 2; rr++) {
                        int row = r + rr * 64;
                        sA[nxt][kq + 0][row] = va[rr].x; sA[nxt][kq + 1][row] = va[rr].y;
                        sA[nxt][kq + 2][row] = va[rr].z; sA[nxt][kq + 3][row] = va[rr].w;
                        *(float4*)&sB[nxt][kk2 + rr * 8][jj2] = vb[rr];
                    }
                    __syncthreads();
                }
            }
            #pragma unroll
            for (int i = 0; i < 8; i++) {
                int gm = m0 + tm * 8 + i;
                if (gm < N) {
                    float* cp = g_AB + (size_t)gm * 512 + part * 128 + tn * 8;
                    *(float4*)cp       = make_float4(acc[i][0], acc[i][1], acc[i][2], acc[i][3]);
                    *(float4*)(cp + 4) = make_float4(acc[i][4], acc[i][5], acc[i][6], acc[i][7]);
                }
            }
        }
        grid_sync();

        // ---- P5: edge aggregation (warp/node, pipelined) + BN partials ----
        {
            const float4* ABv = (const float4*)g_AB;
            const float4* Tf4 = (const float4*)(g_Tf + (size_t)l * (NBINS + 1) * HID);
            const float4* Ts4 = (const float4*)(g_Ts + (size_t)l * (NBINS + 1) * HID);
            float ps0 = 0, ps1 = 0, ps2 = 0, ps3 = 0;
            float pq0 = 0, pq1 = 0, pq2 = 0, pq3 = 0;

            for (int node = gwarp; node < N; node += nwarp) {
                float4 af  = ABv[(size_t)node * 128 + lane];
                float4 as_ = ABv[(size_t)node * 128 + 64 + lane];
                float4 acc = make_float4(0.f, 0.f, 0.f, 0.f);

                int beg = g_rowptr[node], end = g_rowptr[node + 1];
                if (beg < end) {
                    int   s = g_csrc[beg];
                    float p = g_cpos[beg];
                    int   k = (int)p;
                    float t = p - (float)k;
                    float4 bfv = ABv[(size_t)s * 128 + 32 + lane];
                    float4 bsv = ABv[(size_t)s * 128 + 96 + lane];
                    float4 f0 = Tf4[(size_t)k * 32 + lane];
                    float4 f1 = Tf4[(size_t)(k + 1) * 32 + lane];
                    float4 s0 = Ts4[(size_t)k * 32 + lane];
                    float4 s1 = Ts4[(size_t)(k + 1) * 32 + lane];

                    #pragma unroll 2
                    for (int i = beg; i < end; i++) {
                        float  tc  = t;
                        float4 cbf = bfv, cbs = bsv, cf0 = f0, cf1 = f1, cs0 = s0, cs1 = s1;
                        if (i + 1 < end) {
                            int   sn = g_csrc[i + 1];
                            float pn = g_cpos[i + 1];
                            int   kn = (int)pn;
                            t   = pn - (float)kn;
                            bfv = ABv[(size_t)sn * 128 + 32 + lane];
                            bsv = ABv[(size_t)sn * 128 + 96 + lane];
                            f0  = Tf4[(size_t)kn * 32 + lane];
                            f1  = Tf4[(size_t)(kn + 1) * 32 + lane];
                            s0  = Ts4[(size_t)kn * 32 + lane];
                            s1  = Ts4[(size_t)(kn + 1) * 32 + lane];
                        }
                        float fx = af.x + cbf.x + cf0.x + tc * (cf1.x - cf0.x);
                        float fy = af.y + cbf.y + cf0.y + tc * (cf1.y - cf0.y);
                        float fz = af.z + cbf.z + cf0.z + tc * (cf1.z - cf0.z);
                        float fw = af.w + cbf.w + cf0.w + tc * (cf1.w - cf0.w);
                        float sx = as_.x + cbs.x + cs0.x + tc * (cs1.x - cs0.x);
                        float sy = as_.y + cbs.y + cs0.y + tc * (cs1.y - cs0.y);
                        float sz = as_.z + cbs.z + cs0.z + tc * (cs1.z - cs0.z);
                        float sw = as_.w + cbs.w + cs0.w + tc * (cs1.w - cs0.w);

                        acc.x += fsigmoid(fx) * fsoftplus(sx);
                        acc.y += fsigmoid(fy) * fsoftplus(sy);
                        acc.z += fsigmoid(fz) * fsoftplus(sz);
                        acc.w += fsigmoid(fw) * fsoftplus(sw);
                    }
                }
                ((float4*)g_agg)[(size_t)node * 32 + lane] = acc;
                ps0 += acc.x; pq0 += acc.x * acc.x;
                ps1 += acc.y; pq1 += acc.y * acc.y;
                ps2 += acc.z; pq2 += acc.z * acc.z;
                ps3 += acc.w; pq3 += acc.w * acc.w;
            }
            // deterministic block reduction of BN partials
            __syncthreads();
            sBN[wid][lane * 4 + 0] = ps0; sBN[wid][128 + lane * 4 + 0] = pq0;
            sBN[wid][lane * 4 + 1] = ps1; sBN[wid][128 + lane * 4 + 1] = pq1;
            sBN[wid][lane * 4 + 2] = ps2; sBN[wid][128 + lane * 4 + 2] = pq2;
            sBN[wid][lane * 4 + 3] = ps3; sBN[wid][128 + lane * 4 + 3] = pq3;
            __syncthreads();
            {
                float s = 0.f;
                #pragma unroll
                for (int w = 0; w < 8; w++) s += sBN[w][tid];
                g_part[blockIdx.x * 256 + tid] = s;
            }
        }
        grid_sync();

        // ---- P6: BN finalize (block 0) ----
        if (blockIdx.x == 0 && tid < 128) {
            float s = 0.f, q = 0.f;
            for (int i = 0; i < NBLOCKS; i++) {
                s += g_part[i * 256 + tid];
                q += g_part[i * 256 + 128 + tid];
            }
            float invN = 1.0f / (float)N;
            float mu   = s * invN;
            float var  = fmaxf(q * invN - mu * mu, 0.0f);
            float sc   = bng[l * HID + tid] * rsqrtf(var + 1e-5f);
            g_bns[tid]       = sc;
            g_bns[128 + tid] = bnb[l * HID + tid] - mu * sc;
        }
        grid_sync();

        // ---- P7: BN-apply + residual + LN + ReLU + residual ----
        {
            const float* lngl = lng + l * HID;
            const float* lnbl = lnb + l * HID;
            for (int node = gwarp; node < N; node += nwarp) {
                float4 a  = ((const float4*)g_agg)[(size_t)node * 32 + lane];
                float4 hv = ((const float4*)g_h)  [(size_t)node * 32 + lane];
                float4 sc = ((const float4*)g_bns)[lane];
                float4 sh = ((const float4*)g_bns)[32 + lane];

                float cx = a.x * sc.x + sh.x + hv.x;
                float cy = a.y * sc.y + sh.y + hv.y;
                float cz = a.z * sc.z + sh.z + hv.z;
                float cw = a.w * sc.w + sh.w + hv.w;

                float sum = cx + cy + cz + cw;
                #pragma unroll
                for (int d = 16; d; d >>= 1) sum += __shfl_xor_sync(0xffffffffu, sum, d);
                float m = sum * (1.0f / 128.0f);

                float dx = cx - m, dy = cy - m, dz = cz - m, dw = cw - m;
                float q = dx * dx + dy * dy + dz * dz + dw * dw;
                #pragma unroll
                for (int d = 16; d; d >>= 1) q += __shfl_xor_sync(0xffffffffu, q, d);
                float rr = rsqrtf(q * (1.0f / 128.0f) + 1e-5f);

                float4 g4 = ((const float4*)lngl)[lane];
                float4 b4 = ((const float4*)lnbl)[lane];
                float4 o;
                o.x = fmaxf(dx * rr * g4.x + b4.x, 0.f) + hv.x;
                o.y = fmaxf(dy * rr * g4.y + b4.y, 0.f) + hv.y;
                o.z = fmaxf(dz * rr * g4.z + b4.z, 0.f) + hv.z;
                o.w = fmaxf(dw * rr * g4.w + b4.w, 0.f) + hv.w;
                ((float4*)g_h)[(size_t)node * 32 + lane] = o;
            }
        }
        grid_sync();
    }

    // ================= P8: final LN + FC (warp/node) ========================
    {
        float* sWfc = &sA[0][0][0];                    // 2688 floats, fits in sA
        for (int i = tid; i < HID * 21; i += NTHREADS) sWfc[i] = Wfc[i];
        __syncthreads();

        for (int node = gwarp; node < N; node += nwarp) {
            float4 hv = ((const float4*)g_h)[(size_t)node * 32 + lane];
            float sum = hv.x + hv.y + hv.z + hv.w;
            #pragma unroll
            for (int d = 16; d; d >>= 1) sum += __shfl_xor_sync(0xffffffffu, sum, d);
            float m = sum * (1.0f / 128.0f);

            float dx = hv.x - m, dy = hv.y - m, dz = hv.z - m, dw = hv.w - m;
            float q = dx * dx + dy * dy + dz * dz + dw * dw;
            #pragma unroll
            for (int d = 16; d; d >>= 1) q += __shfl_xor_sync(0xffffffffu, q, d);
            float rr = rsqrtf(q * (1.0f / 128.0f) + 1e-5f);

            float4 g4 = ((const float4*)lnog)[lane];
            float4 b4 = ((const float4*)lnob)[lane];
            float h0 = dx * rr * g4.x + b4.x;
            float h1 = dy * rr * g4.y + b4.y;
            float h2 = dz * rr * g4.z + b4.z;
            float h3 = dw * rr * g4.w + b4.w;

            const float* wp = sWfc + (lane * 4) * 21;
            #pragma unroll
            for (int cls = 0; cls < 21; cls++) {
                float p = h0 * wp[cls] + h1 * wp[21 + cls]
                        + h2 * wp[42 + cls] + h3 * wp[63 + cls];
                #pragma unroll
                for (int d = 16; d; d >>= 1) p += __shfl_xor_sync(0xffffffffu, p, d);
                if (lane == 0) out[(size_t)node * 21 + cls] = p + bfc[cls];
            }
        }
    }
}

// ------------------------------- launch ------------------------------------
extern "C" void kernel_launch(void* const* d_in, const int* in_sizes, int n_in,
                              void* d_out, int out_size) {
    const float* x     = (const float*)d_in[0];
    const int*   ei    = (const int*)  d_in[1];
    const float* dist  = (const float*)d_in[2];
    const float* Wn    = (const float*)d_in[3];
    const float* bn    = (const float*)d_in[4];
    const float* Wf    = (const float*)d_in[5];
    const float* bf    = (const float*)d_in[6];
    const float* Ws    = (const float*)d_in[7];
    const float* bs    = (const float*)d_in[8];
    const float* bng   = (const float*)d_in[9];
    const float* bnb   = (const float*)d_in[10];
    const float* lng   = (const float*)d_in[11];
    const float* lnb   = (const float*)d_in[12];
    const float* lnog  = (const float*)d_in[13];
    const float* lnob  = (const float*)d_in[14];
    const float* Wfc   = (const float*)d_in[15];
    const float* bfc   = (const float*)d_in[16];

    const int N = in_sizes[0] / 6;        // 20000
    const int E = in_sizes[2];            // 320000
    int L = in_sizes[6] / HID;            // 4
    if (L > LMAX) L = LMAX;

    mega_kernel<<<NBLOCKS, NTHREADS>>>(x, ei, dist, Wn, bn, Wf, bf, Ws, bs,
                                       bng, bnb, lng, lnb, lnog, lnob, Wfc, bfc,
                                       (float*)d_out, N, E, L);
}

// round 11
// speedup vs baseline: 23.6205x; 1.0094x over previous
#include <cuda_runtime.h>
#include <cuda_fp16.h>
#include <math.h>

// ---------------------------------------------------------------------------
// Struct2SeqGCN as ONE persistent kernel (grid-wide barriers between phases).
// N=20000 nodes, E=320000 edges, H=128, 4 layers, 16 RBF gaussians.
// fp16 (value,delta) lerp tables + fp16 src-node terms; width-2 edge pipeline.
// ---------------------------------------------------------------------------

#define NMAX     20000
#define EMAX     320000
#define HID      128
#define NBINS    2048
#define LMAX     4
#define NBLOCKS  296            // 2 blocks/SM on 148 SMs (guaranteed resident)
#define NTHREADS 256

// ------------------------- static scratch (no allocs) ----------------------
__device__ __align__(16) float  g_h   [NMAX * HID];
__device__ __align__(16) float  g_A2  [NMAX * 256];        // [Af|As] fp32 per node
__device__ __align__(16) __half g_Bh  [NMAX * 256];        // [Bf|Bs] fp16 per node
__device__ __align__(16) float  g_agg [NMAX * HID];
__device__ __align__(16) __half g_Tf16[(size_t)LMAX * NBINS * 256]; // (v,d) pairs
__device__ __align__(16) __half g_Ts16[(size_t)LMAX * NBINS * 256];
__device__ int   g_degcur[2 * NMAX];
__device__ int   g_rowptr[NMAX + 1];
__device__ __align__(8) int2 g_edge[EMAX];                 // (src, pos-bits)
__device__ __align__(16) float g_part[NBLOCKS * 2 * HID];
__device__ __align__(16) float g_bns [2 * HID];

// grid barrier (zero-initialized; gen monotonic across replays)
__device__ volatile unsigned g_bar_gen;
__device__ unsigned          g_bar_cnt;

__device__ __forceinline__ void grid_sync() {
    __syncthreads();
    if (threadIdx.x == 0) {
        __threadfence();
        unsigned gen = g_bar_gen;
        if (atomicAdd(&g_bar_cnt, 1u) == NBLOCKS - 1) {
            g_bar_cnt = 0;
            __threadfence();
            g_bar_gen = gen + 1;
        } else {
            while (g_bar_gen == gen) { __nanosleep(64); }
        }
        __threadfence();
    }
    __syncthreads();
}

__device__ __forceinline__ float fsigmoid(float x) {
    return __fdividef(1.0f, 1.0f + __expf(-x));
}
__device__ __forceinline__ float fsoftplus(float x) {
    return fmaxf(x, 0.0f) + __logf(1.0f + __expf(-fabsf(x)));
}

// ----------------------- packed per-edge register set ----------------------
struct EP {
    uint4 tf, ts;   // 4x half2 (v,d) per gate for this lane's 4 channels
    uint2 b1, b2;   // 4x half Bf, 4x half Bs
    float t;
};

__device__ __forceinline__ void ep_load(int idx, int lane, size_t lrow, EP& r) {
    int2 e = g_edge[idx];
    float p = __int_as_float(e.y);
    int k = (int)p;
    r.t = p - (float)k;
    const __half* tf = g_Tf16 + (lrow + (size_t)k) * 256;
    const __half* ts = g_Ts16 + (lrow + (size_t)k) * 256;
    r.tf = *(const uint4*)(tf + 8 * lane);
    r.ts = *(const uint4*)(ts + 8 * lane);
    const __half* B = g_Bh + (size_t)e.x * 256;
    r.b1 = *(const uint2*)(B + 4 * lane);
    r.b2 = *(const uint2*)(B + 128 + 4 * lane);
}

__device__ __forceinline__ void ep_acc(const EP& r, const float4 af, const float4 as_,
                                       float m, float4& acc) {
    const __half2* tf = (const __half2*)&r.tf;
    const __half2* ts = (const __half2*)&r.ts;
    const __half2* b1 = (const __half2*)&r.b1;
    const __half2* b2 = (const __half2*)&r.b2;
    float2 bfa = __half22float2(b1[0]), bfb = __half22float2(b1[1]);
    float2 bsa = __half22float2(b2[0]), bsb = __half22float2(b2[1]);
    float2 vd;
    vd = __half22float2(tf[0]); float f0 = af.x + bfa.x + vd.x + r.t * vd.y;
    vd = __half22float2(tf[1]); float f1 = af.y + bfa.y + vd.x + r.t * vd.y;
    vd = __half22float2(tf[2]); float f2 = af.z + bfb.x + vd.x + r.t * vd.y;
    vd = __half22float2(tf[3]); float f3 = af.w + bfb.y + vd.x + r.t * vd.y;
    vd = __half22float2(ts[0]); float s0 = as_.x + bsa.x + vd.x + r.t * vd.y;
    vd = __half22float2(ts[1]); float s1 = as_.y + bsa.y + vd.x + r.t * vd.y;
    vd = __half22float2(ts[2]); float s2 = as_.z + bsb.x + vd.x + r.t * vd.y;
    vd = __half22float2(ts[3]); float s3 = as_.w + bsb.y + vd.x + r.t * vd.y;
    acc.x += m * (fsigmoid(f0) * fsoftplus(s0));
    acc.y += m * (fsigmoid(f1) * fsoftplus(s1));
    acc.z += m * (fsigmoid(f2) * fsoftplus(s2));
    acc.w += m * (fsigmoid(f3) * fsoftplus(s3));
}

// ---------------------------------------------------------------------------
__global__ __launch_bounds__(NTHREADS, 2)
void mega_kernel(const float* __restrict__ x, const int* __restrict__ ei,
                 const float* __restrict__ dist,
                 const float* __restrict__ Wn, const float* __restrict__ bnode,
                 const float* __restrict__ Wf, const float* __restrict__ bfp,
                 const float* __restrict__ Ws, const float* __restrict__ bsp,
                 const float* __restrict__ bng, const float* __restrict__ bnb,
                 const float* __restrict__ lng, const float* __restrict__ lnb,
                 const float* __restrict__ lnog, const float* __restrict__ lnob,
                 const float* __restrict__ Wfc, const float* __restrict__ bfc,
                 float* __restrict__ out, int N, int E, int L)
{
    __shared__ __align__(16) float sA[2][16][132];
    __shared__ __align__(16) float sB[2][16][128];
    __shared__ __align__(16) float sBN[8][256];

    const int tid   = threadIdx.x;
    const int gtid  = blockIdx.x * NTHREADS + tid;
    const int nth   = NBLOCKS * NTHREADS;
    const int lane  = tid & 31;
    const int wid   = tid >> 5;
    const int gwarp = blockIdx.x * (NTHREADS / 32) + wid;
    const int nwarp = NBLOCKS * (NTHREADS / 32);
    const int Z     = 2 * HID + 16;                  // 272

    // ================= P0: zero degcur, embed, (v,d) fp16 tables ============
    for (int i = gtid; i < 2 * NMAX; i += nth) g_degcur[i] = 0;

    for (int i = gtid; i < N * HID; i += nth) {
        int n = i >> 7, c = i & 127;
        float acc = bnode[c];
        #pragma unroll
        for (int k = 0; k < 6; k++) acc += x[n * 6 + k] * Wn[k * HID + c];
        g_h[i] = acc;
    }

    for (int i = gtid; i < L * NBINS * HID; i += nth) {
        int l   = i / (NBINS * HID);
        int rem = i - l * (NBINS * HID);
        int b = rem >> 7, c = rem & 127;
        const float* Wfe = Wf + (size_t)l * Z * HID + 256 * HID;
        const float* Wse = Ws + (size_t)l * Z * HID + 256 * HID;
        float d0 = (float)b       * (8.0f / (float)NBINS);
        float d1 = (float)(b + 1) * (8.0f / (float)NBINS);
        float vf0 = bfp[l * HID + c], vf1 = vf0;
        float vs0 = bsp[l * HID + c], vs1 = vs0;
        #pragma unroll
        for (int g = 0; g < 16; g++) {
            float off = (float)g * (8.0f / 15.0f);
            float t0 = d0 - off, t1 = d1 - off;
            float e0 = expf(-1.7578125f * t0 * t0);   // COEFF = -0.5/(8/15)^2
            float e1 = expf(-1.7578125f * t1 * t1);
            float wf = Wfe[g * HID + c], ws = Wse[g * HID + c];
            vf0 += e0 * wf; vf1 += e1 * wf;
            vs0 += e0 * ws; vs1 += e1 * ws;
        }
        size_t h2idx = ((size_t)l * NBINS + b) * 128 + c;
        ((__half2*)g_Tf16)[h2idx] =
            __halves2half2(__float2half_rn(vf0), __float2half_rn(vf1 - vf0));
        ((__half2*)g_Ts16)[h2idx] =
            __halves2half2(__float2half_rn(vs0), __float2half_rn(vs1 - vs0));
    }
    grid_sync();

    // ================= P1: degree histogram =================================
    for (int e = gtid; e < E; e += nth) atomicAdd(&g_degcur[ei[E + e]], 1);
    grid_sync();

    // ================= P2: exclusive scan (block 0, warp 0) =================
    if (blockIdx.x == 0 && wid == 0) {
        int carry = 0;
        for (int base = 0; base < N; base += 32) {
            int i = base + lane;
            int v = (i < N) ? g_degcur[i] : 0;
            int xs = v;
            #pragma unroll
            for (int d = 1; d < 32; d <<= 1) {
                int y = __shfl_up_sync(0xffffffffu, xs, d);
                if (lane >= d) xs += y;
            }
            if (i < N) g_rowptr[i] = carry + xs - v;
            carry += __shfl_sync(0xffffffffu, xs, 31);
        }
        if (lane == 0) g_rowptr[N] = carry;
    }
    grid_sync();

    // ================= P3: scatter edges into CSR (packed records) ==========
    for (int e = gtid; e < E; e += nth) {
        int s = ei[e];
        int d = ei[E + e];
        int pos = g_rowptr[d] + atomicAdd(&g_degcur[NMAX + d], 1);
        float p = dist[e] * ((float)NBINS / 8.0f);
        p = fminf(fmaxf(p, 0.0f), (float)NBINS - 0.001f);
        g_edge[pos] = make_int2(s, __float_as_int(p));
    }
    grid_sync();

    const int mtiles = (N + 127) / 128;

    // ========================== layer loop ==================================
    for (int l = 0; l < L; l++) {
        const float* Wfl = Wf + (size_t)l * Z * HID;
        const float* Wsl = Ws + (size_t)l * Z * HID;

        // ---- P4: node precompute GEMM  h[Nx128] @ W[128x512] ----
        for (int job = blockIdx.x; job < 4 * mtiles; job += NBLOCKS) {
            __syncthreads();
            int part = job / mtiles;         // 0:Af 1:Bf 2:As 3:Bs
            int m0   = (job - part * mtiles) * 128;
            const float* Bp = ((part < 2) ? Wfl : Wsl) + (part & 1) * (HID * HID);

            int tm = tid >> 4, tn = tid & 15;
            float acc[8][8] = {};
            int r   = tid >> 2;
            int kq  = (tid & 3) * 4;
            int kk2 = tid >> 5;
            int jj2 = (tid & 31) * 4;

            #pragma unroll
            for (int rr = 0; rr < 2; rr++) {
                int row = r + rr * 64;
                int gm  = m0 + row;
                float4 v = (gm < N) ? *(const float4*)(g_h + (size_t)gm * HID + kq)
                                    : make_float4(0.f, 0.f, 0.f, 0.f);
                sA[0][kq + 0][row] = v.x; sA[0][kq + 1][row] = v.y;
                sA[0][kq + 2][row] = v.z; sA[0][kq + 3][row] = v.w;
                float4 w = *(const float4*)(Bp + (size_t)(kk2 + rr * 8) * HID + jj2);
                *(float4*)&sB[0][kk2 + rr * 8][jj2] = w;
            }
            __syncthreads();

            #pragma unroll
            for (int kt = 0; kt < 8; kt++) {
                int cur = kt & 1, nxt = cur ^ 1;
                float4 va[2], vb[2];
                if (kt < 7) {
                    int k0 = (kt + 1) * 16;
                    #pragma unroll
                    for (int rr = 0; rr < 2; rr++) {
                        int gm = m0 + r + rr * 64;
                        va[rr] = (gm < N) ? *(const float4*)(g_h + (size_t)gm * HID + k0 + kq)
                                          : make_float4(0.f, 0.f, 0.f, 0.f);
                        vb[rr] = *(const float4*)(Bp + (size_t)(k0 + kk2 + rr * 8) * HID + jj2);
                    }
                }
                #pragma unroll
                for (int kki = 0; kki < 16; kki++) {
                    float a[8], bb[8];
                    *(float4*)&a[0]  = *(float4*)&sA[cur][kki][tm * 8];
                    *(float4*)&a[4]  = *(float4*)&sA[cur][kki][tm * 8 + 4];
                    *(float4*)&bb[0] = *(float4*)&sB[cur][kki][tn * 8];
                    *(float4*)&bb[4] = *(float4*)&sB[cur][kki][tn * 8 + 4];
                    #pragma unroll
                    for (int i = 0; i < 8; i++)
                        #pragma unroll
                        for (int jj = 0; jj < 8; jj++)
                            acc[i][jj] += a[i] * bb[jj];
                }
                if (kt < 7) {
                    #pragma unroll
                    for (int rr = 0; rr < 2; rr++) {
                        int row = r + rr * 64;
                        sA[nxt][kq + 0][row] = va[rr].x; sA[nxt][kq + 1][row] = va[rr].y;
                        sA[nxt][kq + 2][row] = va[rr].z; sA[nxt][kq + 3][row] = va[rr].w;
                        *(float4*)&sB[nxt][kk2 + rr * 8][jj2] = vb[rr];
                    }
                    __syncthreads();
                }
            }
            // epilogue: parts 0/2 -> fp32 g_A2, parts 1/3 -> fp16 g_Bh
            #pragma unroll
            for (int i = 0; i < 8; i++) {
                int gm = m0 + tm * 8 + i;
                if (gm < N) {
                    if ((part & 1) == 0) {
                        float* cp = g_A2 + (size_t)gm * 256 + (part ? 128 : 0) + tn * 8;
                        *(float4*)cp       = make_float4(acc[i][0], acc[i][1], acc[i][2], acc[i][3]);
                        *(float4*)(cp + 4) = make_float4(acc[i][4], acc[i][5], acc[i][6], acc[i][7]);
                    } else {
                        __half* hp = g_Bh + (size_t)gm * 256 + ((part == 1) ? 0 : 128) + tn * 8;
                        __half2 p0 = __floats2half2_rn(acc[i][0], acc[i][1]);
                        __half2 p1 = __floats2half2_rn(acc[i][2], acc[i][3]);
                        __half2 p2 = __floats2half2_rn(acc[i][4], acc[i][5]);
                        __half2 p3 = __floats2half2_rn(acc[i][6], acc[i][7]);
                        uint4 u;
                        u.x = *(unsigned*)&p0; u.y = *(unsigned*)&p1;
                        u.z = *(unsigned*)&p2; u.w = *(unsigned*)&p3;
                        *(uint4*)hp = u;
                    }
                }
            }
        }
        grid_sync();

        // ---- P5: edge aggregation (warp/node, width-2 pipeline) + BN partials
        {
            const float4* A2v = (const float4*)g_A2;   // 64 float4 per node
            const size_t lrow = (size_t)l * NBINS;
            float ps0 = 0, ps1 = 0, ps2 = 0, ps3 = 0;
            float pq0 = 0, pq1 = 0, pq2 = 0, pq3 = 0;

            for (int node = gwarp; node < N; node += nwarp) {
                float4 af  = A2v[(size_t)node * 64 + lane];
                float4 as_ = A2v[(size_t)node * 64 + 32 + lane];
                float4 acc = make_float4(0.f, 0.f, 0.f, 0.f);

                int beg = g_rowptr[node], end = g_rowptr[node + 1];
                if (beg < end) {
                    EP c0, c1, n0, n1;
                    int j1 = min(beg + 1, end - 1);
                    float cm = (beg + 1 < end) ? 1.f : 0.f;
                    ep_load(beg, lane, lrow, c0);
                    ep_load(j1, lane, lrow, c1);
                    for (int i = beg; i < end; i += 2) {
                        int nx = i + 2;
                        bool more = nx < end;
                        float nm = 0.f;
                        if (more) {
                            int k1 = min(nx + 1, end - 1);
                            nm = (nx + 1 < end) ? 1.f : 0.f;
                            ep_load(nx, lane, lrow, n0);
                            ep_load(k1, lane, lrow, n1);
                        }
                        ep_acc(c0, af, as_, 1.f, acc);
                        ep_acc(c1, af, as_, cm, acc);
                        if (more) { c0 = n0; c1 = n1; cm = nm; }
                    }
                }
                ((float4*)g_agg)[(size_t)node * 32 + lane] = acc;
                ps0 += acc.x; pq0 += acc.x * acc.x;
                ps1 += acc.y; pq1 += acc.y * acc.y;
                ps2 += acc.z; pq2 += acc.z * acc.z;
                ps3 += acc.w; pq3 += acc.w * acc.w;
            }
            __syncthreads();
            sBN[wid][lane * 4 + 0] = ps0; sBN[wid][128 + lane * 4 + 0] = pq0;
            sBN[wid][lane * 4 + 1] = ps1; sBN[wid][128 + lane * 4 + 1] = pq1;
            sBN[wid][lane * 4 + 2] = ps2; sBN[wid][128 + lane * 4 + 2] = pq2;
            sBN[wid][lane * 4 + 3] = ps3; sBN[wid][128 + lane * 4 + 3] = pq3;
            __syncthreads();
            {
                float s = 0.f;
                #pragma unroll
                for (int w = 0; w < 8; w++) s += sBN[w][tid];
                g_part[blockIdx.x * 256 + tid] = s;
            }
        }
        grid_sync();

        // ---- P6: BN finalize (block 0) ----
        if (blockIdx.x == 0 && tid < 128) {
            float s = 0.f, q = 0.f;
            for (int i = 0; i < NBLOCKS; i++) {
                s += g_part[i * 256 + tid];
                q += g_part[i * 256 + 128 + tid];
            }
            float invN = 1.0f / (float)N;
            float mu   = s * invN;
            float var  = fmaxf(q * invN - mu * mu, 0.0f);
            float sc   = bng[l * HID + tid] * rsqrtf(var + 1e-5f);
            g_bns[tid]       = sc;
            g_bns[128 + tid] = bnb[l * HID + tid] - mu * sc;
        }
        grid_sync();

        // ---- P7: BN-apply + residual + LN + ReLU + residual ----
        {
            const float* lngl = lng + l * HID;
            const float* lnbl = lnb + l * HID;
            for (int node = gwarp; node < N; node += nwarp) {
                float4 a  = ((const float4*)g_agg)[(size_t)node * 32 + lane];
                float4 hv = ((const float4*)g_h)  [(size_t)node * 32 + lane];
                float4 sc = ((const float4*)g_bns)[lane];
                float4 sh = ((const float4*)g_bns)[32 + lane];

                float cx = a.x * sc.x + sh.x + hv.x;
                float cy = a.y * sc.y + sh.y + hv.y;
                float cz = a.z * sc.z + sh.z + hv.z;
                float cw = a.w * sc.w + sh.w + hv.w;

                float sum = cx + cy + cz + cw;
                #pragma unroll
                for (int d = 16; d; d >>= 1) sum += __shfl_xor_sync(0xffffffffu, sum, d);
                float m = sum * (1.0f / 128.0f);

                float dx = cx - m, dy = cy - m, dz = cz - m, dw = cw - m;
                float q = dx * dx + dy * dy + dz * dz + dw * dw;
                #pragma unroll
                for (int d = 16; d; d >>= 1) q += __shfl_xor_sync(0xffffffffu, q, d);
                float rr = rsqrtf(q * (1.0f / 128.0f) + 1e-5f);

                float4 g4 = ((const float4*)lngl)[lane];
                float4 b4 = ((const float4*)lnbl)[lane];
                float4 o;
                o.x = fmaxf(dx * rr * g4.x + b4.x, 0.f) + hv.x;
                o.y = fmaxf(dy * rr * g4.y + b4.y, 0.f) + hv.y;
                o.z = fmaxf(dz * rr * g4.z + b4.z, 0.f) + hv.z;
                o.w = fmaxf(dw * rr * g4.w + b4.w, 0.f) + hv.w;
                ((float4*)g_h)[(size_t)node * 32 + lane] = o;
            }
        }
        grid_sync();
    }

    // ================= P8: final LN + FC (warp/node) ========================
    {
        float* sWfc = &sA[0][0][0];                    // 2688 floats, fits
        for (int i = tid; i < HID * 21; i += NTHREADS) sWfc[i] = Wfc[i];
        __syncthreads();

        for (int node = gwarp; node < N; node += nwarp) {
            float4 hv = ((const float4*)g_h)[(size_t)node * 32 + lane];
            float sum = hv.x + hv.y + hv.z + hv.w;
            #pragma unroll
            for (int d = 16; d; d >>= 1) sum += __shfl_xor_sync(0xffffffffu, sum, d);
            float m = sum * (1.0f / 128.0f);

            float dx = hv.x - m, dy = hv.y - m, dz = hv.z - m, dw = hv.w - m;
            float q = dx * dx + dy * dy + dz * dz + dw * dw;
            #pragma unroll
            for (int d = 16; d; d >>= 1) q += __shfl_xor_sync(0xffffffffu, q, d);
            float rr = rsqrtf(q * (1.0f / 128.0f) + 1e-5f);

            float4 g4 = ((const float4*)lnog)[lane];
            float4 b4 = ((const float4*)lnob)[lane];
            float h0 = dx * rr * g4.x + b4.x;
            float h1 = dy * rr * g4.y + b4.y;
            float h2 = dz * rr * g4.z + b4.z;
            float h3 = dw * rr * g4.w + b4.w;

            const float* wp = sWfc + (lane * 4) * 21;
            #pragma unroll
            for (int cls = 0; cls < 21; cls++) {
                float p = h0 * wp[cls] + h1 * wp[21 + cls]
                        + h2 * wp[42 + cls] + h3 * wp[63 + cls];
                #pragma unroll
                for (int d = 16; d; d >>= 1) p += __shfl_xor_sync(0xffffffffu, p, d);
                if (lane == 0) out[(size_t)node * 21 + cls] = p + bfc[cls];
            }
        }
    }
}

// ------------------------------- launch ------------------------------------
extern "C" void kernel_launch(void* const* d_in, const int* in_sizes, int n_in,
                              void* d_out, int out_size) {
    const float* x     = (const float*)d_in[0];
    const int*   ei    = (const int*)  d_in[1];
    const float* dist  = (const float*)d_in[2];
    const float* Wn    = (const float*)d_in[3];
    const float* bn    = (const float*)d_in[4];
    const float* Wf    = (const float*)d_in[5];
    const float* bf    = (const float*)d_in[6];
    const float* Ws    = (const float*)d_in[7];
    const float* bs    = (const float*)d_in[8];
    const float* bng   = (const float*)d_in[9];
    const float* bnb   = (const float*)d_in[10];
    const float* lng   = (const float*)d_in[11];
    const float* lnb   = (const float*)d_in[12];
    const float* lnog  = (const float*)d_in[13];
    const float* lnob  = (const float*)d_in[14];
    const float* Wfc   = (const float*)d_in[15];
    const float* bfc   = (const float*)d_in[16];

    const int N = in_sizes[0] / 6;        // 20000
    const int E = in_sizes[2];            // 320000
    int L = in_sizes[6] / HID;            // 4
    if (L > LMAX) L = LMAX;

    mega_kernel<<<NBLOCKS, NTHREADS>>>(x, ei, dist, Wn, bn, Wf, bf, Ws, bs,
                                       bng, bnb, lng, lnb, lnog, lnob, Wfc, bfc,
                                       (float*)d_out, N, E, L);
}

// round 14
// speedup vs baseline: 28.0694x; 1.1883x over previous
#include <cuda_runtime.h>
#include <cuda_fp16.h>
#include <math.h>

// ---------------------------------------------------------------------------
// Struct2SeqGCN as ONE persistent kernel (grid-wide barriers between phases).
// N=20000, E=320000, H=128, 4 layers. 3 blocks/SM for occupancy; cheap table
// build (exps amortized per bin); width-1 prefetch agg; 128x64 GEMM tiles.
// ---------------------------------------------------------------------------

#define NMAX     20000
#define EMAX     320000
#define HID      128
#define NBINS    2048
#define LMAX     4
#define NBLOCKS  444            // 3 blocks/SM on 148 SMs (GB300 has 152)
#define NTHREADS 256

// ------------------------- static scratch (no allocs) ----------------------
__device__ __align__(16) float  g_h   [NMAX * HID];
__device__ __align__(16) float  g_A2  [NMAX * 256];        // [Af|As] fp32
__device__ __align__(16) __half g_Bh  [NMAX * 256];        // [Bf|Bs] fp16
__device__ __align__(16) float  g_agg [NMAX * HID];
__device__ __align__(16) __half g_Tf16[(size_t)LMAX * NBINS * 256]; // (v,d)
__device__ __align__(16) __half g_Ts16[(size_t)LMAX * NBINS * 256];
__device__ int   g_degcur[2 * NMAX];
__device__ int   g_rowptr[NMAX + 1];
__device__ __align__(8) int2 g_edge[EMAX];                 // (src, pos-bits)
__device__ __align__(16) float g_part[NBLOCKS * 2 * HID];
__device__ __align__(16) float g_bns [2 * HID];

// grid barrier (zero-initialized; gen monotonic across replays)
__device__ volatile unsigned g_bar_gen;
__device__ unsigned          g_bar_cnt;

__device__ __forceinline__ void grid_sync() {
    __syncthreads();
    if (threadIdx.x == 0) {
        __threadfence();
        unsigned gen = g_bar_gen;
        if (atomicAdd(&g_bar_cnt, 1u) == NBLOCKS - 1) {
            g_bar_cnt = 0;
            __threadfence();
            g_bar_gen = gen + 1;
        } else {
            while (g_bar_gen == gen) { __nanosleep(64); }
        }
        __threadfence();
    }
    __syncthreads();
}

__device__ __forceinline__ float fsigmoid(float x) {
    return __fdividef(1.0f, 1.0f + __expf(-x));
}
__device__ __forceinline__ float fsoftplus(float x) {
    return fmaxf(x, 0.0f) + __logf(1.0f + __expf(-fabsf(x)));
}

// ----------------------- packed per-edge register set ----------------------
struct EP {
    uint4 tf, ts;   // 4x half2 (v,d) per gate for this lane's 4 channels
    uint2 b1, b2;   // 4x half Bf, 4x half Bs
    float t;
};

__device__ __forceinline__ void ep_load(int idx, int lane, size_t lrow, EP& r) {
    int2 e = g_edge[idx];
    float p = __int_as_float(e.y);
    int k = (int)p;
    r.t = p - (float)k;
    const __half* tf = g_Tf16 + (lrow + (size_t)k) * 256;
    const __half* ts = g_Ts16 + (lrow + (size_t)k) * 256;
    r.tf = *(const uint4*)(tf + 8 * lane);
    r.ts = *(const uint4*)(ts + 8 * lane);
    const __half* B = g_Bh + (size_t)e.x * 256;
    r.b1 = *(const uint2*)(B + 4 * lane);
    r.b2 = *(const uint2*)(B + 128 + 4 * lane);
}

__device__ __forceinline__ void ep_acc(const EP& r, const float4 af, const float4 as_,
                                       float4& acc) {
    const __half2* tf = (const __half2*)&r.tf;
    const __half2* ts = (const __half2*)&r.ts;
    const __half2* b1 = (const __half2*)&r.b1;
    const __half2* b2 = (const __half2*)&r.b2;
    float2 bfa = __half22float2(b1[0]), bfb = __half22float2(b1[1]);
    float2 bsa = __half22float2(b2[0]), bsb = __half22float2(b2[1]);
    float2 vd;
    vd = __half22float2(tf[0]); float f0 = af.x + bfa.x + vd.x + r.t * vd.y;
    vd = __half22float2(tf[1]); float f1 = af.y + bfa.y + vd.x + r.t * vd.y;
    vd = __half22float2(tf[2]); float f2 = af.z + bfb.x + vd.x + r.t * vd.y;
    vd = __half22float2(tf[3]); float f3 = af.w + bfb.y + vd.x + r.t * vd.y;
    vd = __half22float2(ts[0]); float s0 = as_.x + bsa.x + vd.x + r.t * vd.y;
    vd = __half22float2(ts[1]); float s1 = as_.y + bsa.y + vd.x + r.t * vd.y;
    vd = __half22float2(ts[2]); float s2 = as_.z + bsb.x + vd.x + r.t * vd.y;
    vd = __half22float2(ts[3]); float s3 = as_.w + bsb.y + vd.x + r.t * vd.y;
    acc.x += fsigmoid(f0) * fsoftplus(s0);
    acc.y += fsigmoid(f1) * fsoftplus(s1);
    acc.z += fsigmoid(f2) * fsoftplus(s2);
    acc.w += fsigmoid(f3) * fsoftplus(s3);
}

// ---------------------------------------------------------------------------
__global__ __launch_bounds__(NTHREADS, 3)
void mega_kernel(const float* __restrict__ x, const int* __restrict__ ei,
                 const float* __restrict__ dist,
                 const float* __restrict__ Wn, const float* __restrict__ bnode,
                 const float* __restrict__ Wf, const float* __restrict__ bfp,
                 const float* __restrict__ Ws, const float* __restrict__ bsp,
                 const float* __restrict__ bng, const float* __restrict__ bnb,
                 const float* __restrict__ lng, const float* __restrict__ lnb,
                 const float* __restrict__ lnog, const float* __restrict__ lnob,
                 const float* __restrict__ Wfc, const float* __restrict__ bfc,
                 float* __restrict__ out, int N, int E, int L)
{
    __shared__ __align__(16) float sm0[4224];   // GEMM A [2][16][132] / table f
    __shared__ __align__(16) float sm1[4224];   // GEMM B [2][16][64]  / table s
    __shared__ __align__(16) float sBN[2048];   // BN partials [8][256]

    const int tid   = threadIdx.x;
    const int gtid  = blockIdx.x * NTHREADS + tid;
    const int nth   = NBLOCKS * NTHREADS;
    const int lane  = tid & 31;
    const int wid   = tid >> 5;
    const int gwarp = blockIdx.x * (NTHREADS / 32) + wid;
    const int nwarp = NBLOCKS * (NTHREADS / 32);
    const int Z     = 2 * HID + 16;                  // 272

    // ================= P0: zero degcur, embed ===============================
    for (int i = gtid; i < 2 * NMAX; i += nth) g_degcur[i] = 0;

    for (int i = gtid; i < N * HID; i += nth) {
        int n = i >> 7, c = i & 127;
        float acc = bnode[c];
        #pragma unroll
        for (int k = 0; k < 6; k++) acc += x[n * 6 + k] * Wn[k * HID + c];
        g_h[i] = acc;
    }

    // ---- P0b: (v,d) fp16 tables, chunked: 32 output bins per job ----------
    // block computes 33 bin-rows (values) into smem, packs (v, v_next - v).
    for (int job = blockIdx.x; job < L * (NBINS / 32); job += NBLOCKS) {
        __syncthreads();
        int l     = job / (NBINS / 32);
        int chunk = job - l * (NBINS / 32);
        int b0    = chunk * 32;
        const float* Wfe = Wf + (size_t)l * Z * HID + 256 * HID;
        const float* Wse = Ws + (size_t)l * Z * HID + 256 * HID;
        const float* bfl = bfp + l * HID;
        const float* bsl = bsp + l * HID;

        for (int idx = tid; idx < 33 * 128; idx += NTHREADS) {
            int bb = idx >> 7, c = idx & 127;
            float d  = (float)(b0 + bb) * (8.0f / (float)NBINS);
            float af = bfl[c], as = bsl[c];
            #pragma unroll
            for (int g = 0; g < 16; g++) {
                float off = (float)g * (8.0f / 15.0f);
                float t = d - off;
                float e = expf(-1.7578125f * t * t);   // COEFF = -0.5/(8/15)^2
                af += e * Wfe[g * HID + c];
                as += e * Wse[g * HID + c];
            }
            sm0[idx] = af;
            sm1[idx] = as;
        }
        __syncthreads();
        for (int idx = tid; idx < 32 * 128; idx += NTHREADS) {
            int bb = idx >> 7, c = idx & 127;
            size_t o = ((size_t)l * NBINS + b0 + bb) * 128 + c;
            float vf = sm0[idx], df = sm0[idx + 128] - vf;
            float vs = sm1[idx], ds = sm1[idx + 128] - vs;
            ((__half2*)g_Tf16)[o] = __floats2half2_rn(vf, df);
            ((__half2*)g_Ts16)[o] = __floats2half2_rn(vs, ds);
        }
    }
    grid_sync();

    // ================= P1: degree histogram =================================
    for (int e = gtid; e < E; e += nth) atomicAdd(&g_degcur[ei[E + e]], 1);
    grid_sync();

    // ================= P2: exclusive scan (block 0, warp 0) =================
    if (blockIdx.x == 0 && wid == 0) {
        int carry = 0;
        for (int base = 0; base < N; base += 32) {
            int i = base + lane;
            int v = (i < N) ? g_degcur[i] : 0;
            int xs = v;
            #pragma unroll
            for (int d = 1; d < 32; d <<= 1) {
                int y = __shfl_up_sync(0xffffffffu, xs, d);
                if (lane >= d) xs += y;
            }
            if (i < N) g_rowptr[i] = carry + xs - v;
            carry += __shfl_sync(0xffffffffu, xs, 31);
        }
        if (lane == 0) g_rowptr[N] = carry;
    }
    grid_sync();

    // ================= P3: scatter edges into CSR ===========================
    for (int e = gtid; e < E; e += nth) {
        int s = ei[e];
        int d = ei[E + e];
        int pos = g_rowptr[d] + atomicAdd(&g_degcur[NMAX + d], 1);
        float p = dist[e] * ((float)NBINS / 8.0f);
        p = fminf(fmaxf(p, 0.0f), (float)NBINS - 0.001f);
        g_edge[pos] = make_int2(s, __float_as_int(p));
    }
    grid_sync();

    const int mtiles = (N + 127) / 128;
    const int gjobs  = 4 * mtiles * 2;   // 4 parts x M-tiles x 2 N-halves

    float (*As_)[16][132] = (float(*)[16][132])sm0;
    float (*Bs_)[16][64]  = (float(*)[16][64])sm1;

    // ========================== layer loop ==================================
    for (int l = 0; l < L; l++) {
        const float* Wfl = Wf + (size_t)l * Z * HID;
        const float* Wsl = Ws + (size_t)l * Z * HID;

        // ---- P4: node precompute GEMM  h[Nx128] @ W[128x512] (128x64 tiles)
        for (int job = blockIdx.x; job < gjobs; job += NBLOCKS) {
            __syncthreads();
            int part = job / (2 * mtiles);       // 0:Af 1:Bf 2:As 3:Bs
            int rem  = job - part * 2 * mtiles;
            int m0   = (rem >> 1) * 128;
            int n0   = (rem & 1) * 64;
            const float* Bp = ((part < 2) ? Wfl : Wsl) + (part & 1) * (HID * HID);

            int tm = tid >> 4, tn = tid & 15;
            float acc[8][4] = {};
            int r   = tid >> 2;
            int kq  = (tid & 3) * 4;
            int kk3 = tid >> 4;
            int j3  = (tid & 15) * 4;

            // prologue: k-tile 0 -> buffer 0
            #pragma unroll
            for (int rr = 0; rr < 2; rr++) {
                int row = r + rr * 64;
                int gm  = m0 + row;
                float4 v = (gm < N) ? *(const float4*)(g_h + (size_t)gm * HID + kq)
                                    : make_float4(0.f, 0.f, 0.f, 0.f);
                As_[0][kq + 0][row] = v.x; As_[0][kq + 1][row] = v.y;
                As_[0][kq + 2][row] = v.z; As_[0][kq + 3][row] = v.w;
            }
            *(float4*)&Bs_[0][kk3][j3] =
                *(const float4*)(Bp + (size_t)kk3 * HID + n0 + j3);
            __syncthreads();

            #pragma unroll
            for (int kt = 0; kt < 8; kt++) {
                int cur = kt & 1, nxt = cur ^ 1;
                float4 va[2], vb;
                if (kt < 7) {
                    int k0 = (kt + 1) * 16;
                    #pragma unroll
                    for (int rr = 0; rr < 2; rr++) {
                        int gm = m0 + r + rr * 64;
                        va[rr] = (gm < N) ? *(const float4*)(g_h + (size_t)gm * HID + k0 + kq)
                                          : make_float4(0.f, 0.f, 0.f, 0.f);
                    }
                    vb = *(const float4*)(Bp + (size_t)(k0 + kk3) * HID + n0 + j3);
                }
                #pragma unroll
                for (int kki = 0; kki < 16; kki++) {
                    float a[8], bb[4];
                    *(float4*)&a[0] = *(float4*)&As_[cur][kki][tm * 8];
                    *(float4*)&a[4] = *(float4*)&As_[cur][kki][tm * 8 + 4];
                    *(float4*)&bb[0] = *(float4*)&Bs_[cur][kki][tn * 4];
                    #pragma unroll
                    for (int i = 0; i < 8; i++)
                        #pragma unroll
                        for (int jj = 0; jj < 4; jj++)
                            acc[i][jj] += a[i] * bb[jj];
                }
                if (kt < 7) {
                    #pragma unroll
                    for (int rr = 0; rr < 2; rr++) {
                        int row = r + rr * 64;
                        As_[nxt][kq + 0][row] = va[rr].x; As_[nxt][kq + 1][row] = va[rr].y;
                        As_[nxt][kq + 2][row] = va[rr].z; As_[nxt][kq + 3][row] = va[rr].w;
                    }
                    *(float4*)&Bs_[nxt][kk3][j3] = vb;
                    __syncthreads();
                }
            }
            // epilogue: parts 0/2 -> fp32 g_A2, parts 1/3 -> fp16 g_Bh
            #pragma unroll
            for (int i = 0; i < 8; i++) {
                int gm = m0 + tm * 8 + i;
                if (gm < N) {
                    int coff = n0 + tn * 4;
                    if ((part & 1) == 0) {
                        float* cp = g_A2 + (size_t)gm * 256 + (part ? 128 : 0) + coff;
                        *(float4*)cp = make_float4(acc[i][0], acc[i][1], acc[i][2], acc[i][3]);
                    } else {
                        __half* hp = g_Bh + (size_t)gm * 256 + ((part == 1) ? 0 : 128) + coff;
                        __half2 p0 = __floats2half2_rn(acc[i][0], acc[i][1]);
                        __half2 p1 = __floats2half2_rn(acc[i][2], acc[i][3]);
                        uint2 u;
                        u.x = *(unsigned*)&p0; u.y = *(unsigned*)&p1;
                        *(uint2*)hp = u;
                    }
                }
            }
        }
        grid_sync();

        // ---- P5: edge aggregation (warp/node, width-1 prefetch) + BN partials
        {
            const float4* A2v = (const float4*)g_A2;   // 64 float4 per node
            const size_t lrow = (size_t)l * NBINS;
            float ps0 = 0, ps1 = 0, ps2 = 0, ps3 = 0;
            float pq0 = 0, pq1 = 0, pq2 = 0, pq3 = 0;

            for (int node = gwarp; node < N; node += nwarp) {
                float4 af  = A2v[(size_t)node * 64 + lane];
                float4 as_ = A2v[(size_t)node * 64 + 32 + lane];
                float4 acc = make_float4(0.f, 0.f, 0.f, 0.f);

                int beg = g_rowptr[node], end = g_rowptr[node + 1];
                if (beg < end) {
                    EP cur, nxt;
                    ep_load(beg, lane, lrow, cur);
                    for (int i = beg; i < end; i++) {
                        if (i + 1 < end) ep_load(i + 1, lane, lrow, nxt);
                        ep_acc(cur, af, as_, acc);
                        cur = nxt;
                    }
                }
                ((float4*)g_agg)[(size_t)node * 32 + lane] = acc;
                ps0 += acc.x; pq0 += acc.x * acc.x;
                ps1 += acc.y; pq1 += acc.y * acc.y;
                ps2 += acc.z; pq2 += acc.z * acc.z;
                ps3 += acc.w; pq3 += acc.w * acc.w;
            }
            __syncthreads();
            sBN[wid * 256 + lane * 4 + 0] = ps0; sBN[wid * 256 + 128 + lane * 4 + 0] = pq0;
            sBN[wid * 256 + lane * 4 + 1] = ps1; sBN[wid * 256 + 128 + lane * 4 + 1] = pq1;
            sBN[wid * 256 + lane * 4 + 2] = ps2; sBN[wid * 256 + 128 + lane * 4 + 2] = pq2;
            sBN[wid * 256 + lane * 4 + 3] = ps3; sBN[wid * 256 + 128 + lane * 4 + 3] = pq3;
            __syncthreads();
            {
                float s = 0.f;
                #pragma unroll
                for (int w = 0; w < 8; w++) s += sBN[w * 256 + tid];
                g_part[blockIdx.x * 256 + tid] = s;
            }
        }
        grid_sync();

        // ---- P6: BN finalize (block 0) ----
        if (blockIdx.x == 0 && tid < 128) {
            float s = 0.f, q = 0.f;
            for (int i = 0; i < NBLOCKS; i++) {
                s += g_part[i * 256 + tid];
                q += g_part[i * 256 + 128 + tid];
            }
            float invN = 1.0f / (float)N;
            float mu   = s * invN;
            float var  = fmaxf(q * invN - mu * mu, 0.0f);
            float sc   = bng[l * HID + tid] * rsqrtf(var + 1e-5f);
            g_bns[tid]       = sc;
            g_bns[128 + tid] = bnb[l * HID + tid] - mu * sc;
        }
        grid_sync();

        // ---- P7: BN-apply + residual + LN + ReLU + residual ----
        {
            const float* lngl = lng + l * HID;
            const float* lnbl = lnb + l * HID;
            for (int node = gwarp; node < N; node += nwarp) {
                float4 a  = ((const float4*)g_agg)[(size_t)node * 32 + lane];
                float4 hv = ((const float4*)g_h)  [(size_t)node * 32 + lane];
                float4 sc = ((const float4*)g_bns)[lane];
                float4 sh = ((const float4*)g_bns)[32 + lane];

                float cx = a.x * sc.x + sh.x + hv.x;
                float cy = a.y * sc.y + sh.y + hv.y;
                float cz = a.z * sc.z + sh.z + hv.z;
                float cw = a.w * sc.w + sh.w + hv.w;

                float sum = cx + cy + cz + cw;
                #pragma unroll
                for (int d = 16; d; d >>= 1) sum += __shfl_xor_sync(0xffffffffu, sum, d);
                float m = sum * (1.0f / 128.0f);

                float dx = cx - m, dy = cy - m, dz = cz - m, dw = cw - m;
                float q = dx * dx + dy * dy + dz * dz + dw * dw;
                #pragma unroll
                for (int d = 16; d; d >>= 1) q += __shfl_xor_sync(0xffffffffu, q, d);
                float rr = rsqrtf(q * (1.0f / 128.0f) + 1e-5f);

                float4 g4 = ((const float4*)lngl)[lane];
                float4 b4 = ((const float4*)lnbl)[lane];
                float4 o;
                o.x = fmaxf(dx * rr * g4.x + b4.x, 0.f) + hv.x;
                o.y = fmaxf(dy * rr * g4.y + b4.y, 0.f) + hv.y;
                o.z = fmaxf(dz * rr * g4.z + b4.z, 0.f) + hv.z;
                o.w = fmaxf(dw * rr * g4.w + b4.w, 0.f) + hv.w;
                ((float4*)g_h)[(size_t)node * 32 + lane] = o;
            }
        }
        grid_sync();
    }

    // ================= P8: final LN + FC (warp/node) ========================
    {
        float* sWfc = sm0;                     // 2688 floats, fits
        for (int i = tid; i < HID * 21; i += NTHREADS) sWfc[i] = Wfc[i];
        __syncthreads();

        for (int node = gwarp; node < N; node += nwarp) {
            float4 hv = ((const float4*)g_h)[(size_t)node * 32 + lane];
            float sum = hv.x + hv.y + hv.z + hv.w;
            #pragma unroll
            for (int d = 16; d; d >>= 1) sum += __shfl_xor_sync(0xffffffffu, sum, d);
            float m = sum * (1.0f / 128.0f);

            float dx = hv.x - m, dy = hv.y - m, dz = hv.z - m, dw = hv.w - m;
            float q = dx * dx + dy * dy + dz * dz + dw * dw;
            #pragma unroll
            for (int d = 16; d; d >>= 1) q += __shfl_xor_sync(0xffffffffu, q, d);
            float rr = rsqrtf(q * (1.0f / 128.0f) + 1e-5f);

            float4 g4 = ((const float4*)lnog)[lane];
            float4 b4 = ((const float4*)lnob)[lane];
            float h0 = dx * rr * g4.x + b4.x;
            float h1 = dy * rr * g4.y + b4.y;
            float h2 = dz * rr * g4.z + b4.z;
            float h3 = dw * rr * g4.w + b4.w;

            const float* wp = sWfc + (lane * 4) * 21;
            #pragma unroll
            for (int cls = 0; cls < 21; cls++) {
                float p = h0 * wp[cls] + h1 * wp[21 + cls]
                        + h2 * wp[42 + cls] + h3 * wp[63 + cls];
                #pragma unroll
                for (int d = 16; d; d >>= 1) p += __shfl_xor_sync(0xffffffffu, p, d);
                if (lane == 0) out[(size_t)node * 21 + cls] = p + bfc[cls];
            }
        }
    }
}

// ------------------------------- launch ------------------------------------
extern "C" void kernel_launch(void* const* d_in, const int* in_sizes, int n_in,
                              void* d_out, int out_size) {
    const float* x     = (const float*)d_in[0];
    const int*   ei    = (const int*)  d_in[1];
    const float* dist  = (const float*)d_in[2];
    const float* Wn    = (const float*)d_in[3];
    const float* bn    = (const float*)d_in[4];
    const float* Wf    = (const float*)d_in[5];
    const float* bf    = (const float*)d_in[6];
    const float* Ws    = (const float*)d_in[7];
    const float* bs    = (const float*)d_in[8];
    const float* bng   = (const float*)d_in[9];
    const float* bnb   = (const float*)d_in[10];
    const float* lng   = (const float*)d_in[11];
    const float* lnb   = (const float*)d_in[12];
    const float* lnog  = (const float*)d_in[13];
    const float* lnob  = (const float*)d_in[14];
    const float* Wfc   = (const float*)d_in[15];
    const float* bfc   = (const float*)d_in[16];

    const int N = in_sizes[0] / 6;        // 20000
    const int E = in_sizes[2];            // 320000
    int L = in_sizes[6] / HID;            // 4
    if (L > LMAX) L = LMAX;

    mega_kernel<<<NBLOCKS, NTHREADS>>>(x, ei, dist, Wn, bn, Wf, bf, Ws, bs,
                                       bng, bnb, lng, lnb, lnog, lnob, Wfc, bfc,
                                       (float*)d_out, N, E, L);
}

// round 15
// speedup vs baseline: 32.5093x; 1.1582x over previous
#include <cuda_runtime.h>
#include <cuda_fp16.h>
#include <math.h>

// ---------------------------------------------------------------------------
// Struct2SeqGCN as ONE persistent kernel. tf32 mma.sync GEMM (tensor pipe),
// tanh-based sigmoid (MUFU reduction), fp16 (v,d) lerp tables, CSR agg.
// N=20000, E=320000, H=128, 4 layers.
// ---------------------------------------------------------------------------

#define NMAX     20000
#define EMAX     320000
#define HID      128
#define NBINS    2048
#define LMAX     4
#define NBLOCKS  444            // 3 blocks/SM on 148 SMs
#define NTHREADS 256

// ------------------------- static scratch (no allocs) ----------------------
__device__ __align__(16) float  g_h   [NMAX * HID];
__device__ __align__(16) float  g_A2  [NMAX * 256];        // [Af|As] fp32
__device__ __align__(16) __half g_Bh  [NMAX * 256];        // [Bf|Bs] fp16
__device__ __align__(16) float  g_agg [NMAX * HID];
__device__ __align__(16) __half g_Tf16[(size_t)LMAX * NBINS * 256]; // (v,d)
__device__ __align__(16) __half g_Ts16[(size_t)LMAX * NBINS * 256];
__device__ int   g_degcur[2 * NMAX];
__device__ int   g_rowptr[NMAX + 1];
__device__ __align__(8) int2 g_edge[EMAX];                 // (src, pos-bits)
__device__ __align__(16) float g_part[NBLOCKS * 2 * HID];
__device__ __align__(16) float g_bns [2 * HID];

// grid barrier (zero-initialized; gen monotonic across replays)
__device__ volatile unsigned g_bar_gen;
__device__ unsigned          g_bar_cnt;

__device__ __forceinline__ void grid_sync() {
    __syncthreads();
    if (threadIdx.x == 0) {
        __threadfence();
        unsigned gen = g_bar_gen;
        if (atomicAdd(&g_bar_cnt, 1u) == NBLOCKS - 1) {
            g_bar_cnt = 0;
            __threadfence();
            g_bar_gen = gen + 1;
        } else {
            while (g_bar_gen == gen) { __nanosleep(64); }
        }
        __threadfence();
    }
    __syncthreads();
}

// sigmoid via single-MUFU tanh: sigmoid(x) = 0.5*tanh(x/2)+0.5
__device__ __forceinline__ float fsigmoid(float x) {
    float t;
    asm("tanh.approx.f32 %0, %1;" : "=f"(t) : "f"(x * 0.5f));
    return fmaf(t, 0.5f, 0.5f);
}
__device__ __forceinline__ float fsoftplus(float x) {
    return fmaxf(x, 0.0f) + __logf(1.0f + __expf(-fabsf(x)));
}

__device__ __forceinline__ unsigned f2tf32(float f) {
    unsigned u;
    asm("cvt.rna.tf32.f32 %0, %1;" : "=r"(u) : "f"(f));
    return u;
}

__device__ __forceinline__ void mma_tf32(float* d, const unsigned* a, const unsigned* b) {
    asm volatile(
        "mma.sync.aligned.m16n8k8.row.col.f32.tf32.tf32.f32 "
        "{%0,%1,%2,%3}, {%4,%5,%6,%7}, {%8,%9}, {%0,%1,%2,%3};"
        : "+f"(d[0]), "+f"(d[1]), "+f"(d[2]), "+f"(d[3])
        : "r"(a[0]), "r"(a[1]), "r"(a[2]), "r"(a[3]), "r"(b[0]), "r"(b[1]));
}

// ----------------------- packed per-edge register set ----------------------
struct EP {
    uint4 tf, ts;   // 4x half2 (v,d) per gate for this lane's 4 channels
    uint2 b1, b2;   // 4x half Bf, 4x half Bs
    float t;
};

__device__ __forceinline__ void ep_load(int idx, int lane, size_t lrow, EP& r) {
    int2 e = g_edge[idx];
    float p = __int_as_float(e.y);
    int k = (int)p;
    r.t = p - (float)k;
    const __half* tf = g_Tf16 + (lrow + (size_t)k) * 256;
    const __half* ts = g_Ts16 + (lrow + (size_t)k) * 256;
    r.tf = *(const uint4*)(tf + 8 * lane);
    r.ts = *(const uint4*)(ts + 8 * lane);
    const __half* B = g_Bh + (size_t)e.x * 256;
    r.b1 = *(const uint2*)(B + 4 * lane);
    r.b2 = *(const uint2*)(B + 128 + 4 * lane);
}

__device__ __forceinline__ void ep_acc(const EP& r, const float4 af, const float4 as_,
                                       float4& acc) {
    const __half2* tf = (const __half2*)&r.tf;
    const __half2* ts = (const __half2*)&r.ts;
    const __half2* b1 = (const __half2*)&r.b1;
    const __half2* b2 = (const __half2*)&r.b2;
    float2 bfa = __half22float2(b1[0]), bfb = __half22float2(b1[1]);
    float2 bsa = __half22float2(b2[0]), bsb = __half22float2(b2[1]);
    float2 vd;
    vd = __half22float2(tf[0]); float f0 = af.x + bfa.x + vd.x + r.t * vd.y;
    vd = __half22float2(tf[1]); float f1 = af.y + bfa.y + vd.x + r.t * vd.y;
    vd = __half22float2(tf[2]); float f2 = af.z + bfb.x + vd.x + r.t * vd.y;
    vd = __half22float2(tf[3]); float f3 = af.w + bfb.y + vd.x + r.t * vd.y;
    vd = __half22float2(ts[0]); float s0 = as_.x + bsa.x + vd.x + r.t * vd.y;
    vd = __half22float2(ts[1]); float s1 = as_.y + bsa.y + vd.x + r.t * vd.y;
    vd = __half22float2(ts[2]); float s2 = as_.z + bsb.x + vd.x + r.t * vd.y;
    vd = __half22float2(ts[3]); float s3 = as_.w + bsb.y + vd.x + r.t * vd.y;
    acc.x += fsigmoid(f0) * fsoftplus(s0);
    acc.y += fsigmoid(f1) * fsoftplus(s1);
    acc.z += fsigmoid(f2) * fsoftplus(s2);
    acc.w += fsigmoid(f3) * fsoftplus(s3);
}

// ---------------------------------------------------------------------------
__global__ __launch_bounds__(NTHREADS, 3)
void mega_kernel(const float* __restrict__ x, const int* __restrict__ ei,
                 const float* __restrict__ dist,
                 const float* __restrict__ Wn, const float* __restrict__ bnode,
                 const float* __restrict__ Wf, const float* __restrict__ bfp,
                 const float* __restrict__ Ws, const float* __restrict__ bsp,
                 const float* __restrict__ bng, const float* __restrict__ bnb,
                 const float* __restrict__ lng, const float* __restrict__ lnb,
                 const float* __restrict__ lnog, const float* __restrict__ lnob,
                 const float* __restrict__ Wfc, const float* __restrict__ bfc,
                 float* __restrict__ out, int N, int E, int L)
{
    // pool: GEMM A tf32 [2][128][20] (5120 u) + B tf32 [2][16][68] (2176 u)
    // reused by table build (17*128*2 floats) and P8 (Wfc cache)
    __shared__ __align__(16) unsigned s_pool[7296];   // 29184 B
    __shared__ __align__(16) float sBN[2048];         //  8192 B

    const int tid   = threadIdx.x;
    const int gtid  = blockIdx.x * NTHREADS + tid;
    const int nth   = NBLOCKS * NTHREADS;
    const int lane  = tid & 31;
    const int wid   = tid >> 5;
    const int gwarp = blockIdx.x * (NTHREADS / 32) + wid;
    const int nwarp = NBLOCKS * (NTHREADS / 32);
    const int Z     = 2 * HID + 16;                  // 272

    // ================= P0: zero degcur, embed ===============================
    for (int i = gtid; i < 2 * NMAX; i += nth) g_degcur[i] = 0;

    for (int i = gtid; i < N * HID; i += nth) {
        int n = i >> 7, c = i & 127;
        float acc = bnode[c];
        #pragma unroll
        for (int k = 0; k < 6; k++) acc += x[n * 6 + k] * Wn[k * HID + c];
        g_h[i] = acc;
    }

    // ---- P0b: (v,d) fp16 tables, 16 output bins per job --------------------
    for (int job = blockIdx.x; job < L * (NBINS / 16); job += NBLOCKS) {
        __syncthreads();
        int l     = job / (NBINS / 16);
        int chunk = job - l * (NBINS / 16);
        int b0    = chunk * 16;
        const float* Wfe = Wf + (size_t)l * Z * HID + 256 * HID;
        const float* Wse = Ws + (size_t)l * Z * HID + 256 * HID;
        const float* bfl = bfp + l * HID;
        const float* bsl = bsp + l * HID;
        float* sm0 = (float*)s_pool;          // 17*128
        float* sm1 = sm0 + 2176;

        for (int idx = tid; idx < 17 * 128; idx += NTHREADS) {
            int bb = idx >> 7, c = idx & 127;
            float d  = (float)(b0 + bb) * (8.0f / (float)NBINS);
            float af = bfl[c], as = bsl[c];
            #pragma unroll
            for (int g = 0; g < 16; g++) {
                float off = (float)g * (8.0f / 15.0f);
                float t = d - off;
                float e = expf(-1.7578125f * t * t);   // COEFF = -0.5/(8/15)^2
                af += e * Wfe[g * HID + c];
                as += e * Wse[g * HID + c];
            }
            sm0[idx] = af;
            sm1[idx] = as;
        }
        __syncthreads();
        for (int idx = tid; idx < 16 * 128; idx += NTHREADS) {
            int bb = idx >> 7, c = idx & 127;
            size_t o = ((size_t)l * NBINS + b0 + bb) * 128 + c;
            float vf = sm0[idx], df = sm0[idx + 128] - vf;
            float vs = sm1[idx], ds = sm1[idx + 128] - vs;
            ((__half2*)g_Tf16)[o] = __floats2half2_rn(vf, df);
            ((__half2*)g_Ts16)[o] = __floats2half2_rn(vs, ds);
        }
    }
    grid_sync();

    // ================= P1: degree histogram =================================
    for (int e = gtid; e < E; e += nth) atomicAdd(&g_degcur[ei[E + e]], 1);
    grid_sync();

    // ================= P2: exclusive scan (block 0, warp 0) =================
    if (blockIdx.x == 0 && wid == 0) {
        int carry = 0;
        for (int base = 0; base < N; base += 32) {
            int i = base + lane;
            int v = (i < N) ? g_degcur[i] : 0;
            int xs = v;
            #pragma unroll
            for (int d = 1; d < 32; d <<= 1) {
                int y = __shfl_up_sync(0xffffffffu, xs, d);
                if (lane >= d) xs += y;
            }
            if (i < N) g_rowptr[i] = carry + xs - v;
            carry += __shfl_sync(0xffffffffu, xs, 31);
        }
        if (lane == 0) g_rowptr[N] = carry;
    }
    grid_sync();

    // ================= P3: scatter edges into CSR ===========================
    for (int e = gtid; e < E; e += nth) {
        int s = ei[e];
        int d = ei[E + e];
        int pos = g_rowptr[d] + atomicAdd(&g_degcur[NMAX + d], 1);
        float p = dist[e] * ((float)NBINS / 8.0f);
        p = fminf(fmaxf(p, 0.0f), (float)NBINS - 0.001f);
        g_edge[pos] = make_int2(s, __float_as_int(p));
    }
    grid_sync();

    const int mtiles = (N + 127) / 128;
    const int gjobs  = 4 * mtiles * 2;   // parts x M-tiles x 2 N-halves

    unsigned* sA = s_pool;          // [2][128*20]
    unsigned* sB = s_pool + 5120;   // [2][16*68]

    // ========================== layer loop ==================================
    for (int l = 0; l < L; l++) {
        const float* Wfl = Wf + (size_t)l * Z * HID;
        const float* Wsl = Ws + (size_t)l * Z * HID;

        // ---- P4: node precompute GEMM via tf32 mma (128x64 tiles) ----
        for (int job = blockIdx.x; job < gjobs; job += NBLOCKS) {
            __syncthreads();
            int part = job / (2 * mtiles);       // 0:Af 1:Bf 2:As 3:Bs
            int rem  = job - part * 2 * mtiles;
            int m0   = (rem >> 1) * 128;
            int n0   = (rem & 1) * 64;
            const float* Bp = ((part < 2) ? Wfl : Wsl) + (part & 1) * (HID * HID);

            const int wm = wid & 3;              // 4 warps over M (32 rows each)
            const int wn = wid >> 2;             // 2 warps over N (32 cols each)
            float acc[2][4][4];
            #pragma unroll
            for (int a = 0; a < 2; a++)
                #pragma unroll
                for (int b = 0; b < 4; b++)
                    #pragma unroll
                    for (int c = 0; c < 4; c++) acc[a][b][c] = 0.f;

            // chunk copy: A 128x16 (cvt tf32), B 16x64 (cvt tf32)
            auto copy_chunk = [&](int kc, int buf) {
                unsigned* dA = sA + buf * 2560;
                #pragma unroll
                for (int ii = 0; ii < 2; ii++) {
                    int i = tid + ii * 256;          // 512 float4 jobs
                    int row = i >> 2, kq = (i & 3) * 4;
                    int gm = m0 + row;
                    float4 v = (gm < N) ? *(const float4*)(g_h + (size_t)gm * HID + kc + kq)
                                        : make_float4(0.f, 0.f, 0.f, 0.f);
                    unsigned* p = dA + row * 20 + kq;
                    p[0] = f2tf32(v.x); p[1] = f2tf32(v.y);
                    p[2] = f2tf32(v.z); p[3] = f2tf32(v.w);
                }
                unsigned* dB = sB + buf * 1088;
                {
                    int kr = tid >> 4, nq = (tid & 15) * 4;   // 256 float4 jobs
                    float4 v = *(const float4*)(Bp + (size_t)(kc + kr) * HID + n0 + nq);
                    unsigned* p = dB + kr * 68 + nq;
                    p[0] = f2tf32(v.x); p[1] = f2tf32(v.y);
                    p[2] = f2tf32(v.z); p[3] = f2tf32(v.w);
                }
            };

            copy_chunk(0, 0);
            __syncthreads();

            #pragma unroll
            for (int c = 0; c < 8; c++) {
                int buf = c & 1;
                if (c < 7) copy_chunk((c + 1) * 16, buf ^ 1);
                const unsigned* cA = sA + buf * 2560;
                const unsigned* cB = sB + buf * 1088;
                #pragma unroll
                for (int ks = 0; ks < 2; ks++) {
                    int k8 = ks * 8;
                    unsigned afr[2][4];
                    #pragma unroll
                    for (int mi = 0; mi < 2; mi++) {
                        int rb = wm * 32 + mi * 16 + (lane >> 2);
                        int cb = k8 + (lane & 3);
                        afr[mi][0] = cA[rb * 20 + cb];
                        afr[mi][1] = cA[(rb + 8) * 20 + cb];
                        afr[mi][2] = cA[rb * 20 + cb + 4];
                        afr[mi][3] = cA[(rb + 8) * 20 + cb + 4];
                    }
                    unsigned bfr[4][2];
                    #pragma unroll
                    for (int ni = 0; ni < 4; ni++) {
                        int nb = wn * 32 + ni * 8 + (lane >> 2);
                        int kb = k8 + (lane & 3);
                        bfr[ni][0] = cB[kb * 68 + nb];
                        bfr[ni][1] = cB[(kb + 4) * 68 + nb];
                    }
                    #pragma unroll
                    for (int mi = 0; mi < 2; mi++)
                        #pragma unroll
                        for (int ni = 0; ni < 4; ni++)
                            mma_tf32(acc[mi][ni], afr[mi], bfr[ni]);
                }
                __syncthreads();
            }

            // epilogue: parts 0/2 -> fp32 g_A2, parts 1/3 -> fp16 g_Bh
            int off = (part & 1) ? ((part == 1) ? 0 : 128) : (part ? 128 : 0);
            #pragma unroll
            for (int mi = 0; mi < 2; mi++) {
                int gr = m0 + wm * 32 + mi * 16 + (lane >> 2);
                #pragma unroll
                for (int ni = 0; ni < 4; ni++) {
                    int col = n0 + wn * 32 + ni * 8 + (lane & 3) * 2;
                    float* d = acc[mi][ni];
                    if ((part & 1) == 0) {
                        if (gr < N)
                            *(float2*)(g_A2 + (size_t)gr * 256 + off + col) =
                                make_float2(d[0], d[1]);
                        if (gr + 8 < N)
                            *(float2*)(g_A2 + (size_t)(gr + 8) * 256 + off + col) =
                                make_float2(d[2], d[3]);
                    } else {
                        if (gr < N)
                            *(__half2*)(g_Bh + (size_t)gr * 256 + off + col) =
                                __floats2half2_rn(d[0], d[1]);
                        if (gr + 8 < N)
                            *(__half2*)(g_Bh + (size_t)(gr + 8) * 256 + off + col) =
                                __floats2half2_rn(d[2], d[3]);
                    }
                }
            }
        }
        grid_sync();

        // ---- P5: edge aggregation (warp/node, prefetch) + BN partials ----
        {
            const float4* A2v = (const float4*)g_A2;   // 64 float4 per node
            const size_t lrow = (size_t)l * NBINS;
            float ps0 = 0, ps1 = 0, ps2 = 0, ps3 = 0;
            float pq0 = 0, pq1 = 0, pq2 = 0, pq3 = 0;

            for (int node = gwarp; node < N; node += nwarp) {
                float4 af  = A2v[(size_t)node * 64 + lane];
                float4 as_ = A2v[(size_t)node * 64 + 32 + lane];
                float4 acc = make_float4(0.f, 0.f, 0.f, 0.f);

                int beg = g_rowptr[node], end = g_rowptr[node + 1];
                if (beg < end) {
                    EP cur, nxt;
                    ep_load(beg, lane, lrow, cur);
                    for (int i = beg; i < end; i++) {
                        if (i + 1 < end) ep_load(i + 1, lane, lrow, nxt);
                        ep_acc(cur, af, as_, acc);
                        cur = nxt;
                    }
                }
                ((float4*)g_agg)[(size_t)node * 32 + lane] = acc;
                ps0 += acc.x; pq0 += acc.x * acc.x;
                ps1 += acc.y; pq1 += acc.y * acc.y;
                ps2 += acc.z; pq2 += acc.z * acc.z;
                ps3 += acc.w; pq3 += acc.w * acc.w;
            }
            __syncthreads();
            sBN[wid * 256 + lane * 4 + 0] = ps0; sBN[wid * 256 + 128 + lane * 4 + 0] = pq0;
            sBN[wid * 256 + lane * 4 + 1] = ps1; sBN[wid * 256 + 128 + lane * 4 + 1] = pq1;
            sBN[wid * 256 + lane * 4 + 2] = ps2; sBN[wid * 256 + 128 + lane * 4 + 2] = pq2;
            sBN[wid * 256 + lane * 4 + 3] = ps3; sBN[wid * 256 + 128 + lane * 4 + 3] = pq3;
            __syncthreads();
            {
                float s = 0.f;
                #pragma unroll
                for (int w = 0; w < 8; w++) s += sBN[w * 256 + tid];
                g_part[blockIdx.x * 256 + tid] = s;
            }
        }
        grid_sync();

        // ---- P6: BN finalize (block 0) ----
        if (blockIdx.x == 0 && tid < 128) {
            float s = 0.f, q = 0.f;
            for (int i = 0; i < NBLOCKS; i++) {
                s += g_part[i * 256 + tid];
                q += g_part[i * 256 + 128 + tid];
            }
            float invN = 1.0f / (float)N;
            float mu   = s * invN;
            float var  = fmaxf(q * invN - mu * mu, 0.0f);
            float sc   = bng[l * HID + tid] * rsqrtf(var + 1e-5f);
            g_bns[tid]       = sc;
            g_bns[128 + tid] = bnb[l * HID + tid] - mu * sc;
        }
        grid_sync();

        // ---- P7: BN-apply + residual + LN + ReLU + residual ----
        {
            const float* lngl = lng + l * HID;
            const float* lnbl = lnb + l * HID;
            for (int node = gwarp; node < N; node += nwarp) {
                float4 a  = ((const float4*)g_agg)[(size_t)node * 32 + lane];
                float4 hv = ((const float4*)g_h)  [(size_t)node * 32 + lane];
                float4 sc = ((const float4*)g_bns)[lane];
                float4 sh = ((const float4*)g_bns)[32 + lane];

                float cx = a.x * sc.x + sh.x + hv.x;
                float cy = a.y * sc.y + sh.y + hv.y;
                float cz = a.z * sc.z + sh.z + hv.z;
                float cw = a.w * sc.w + sh.w + hv.w;

                float sum = cx + cy + cz + cw;
                #pragma unroll
                for (int d = 16; d; d >>= 1) sum += __shfl_xor_sync(0xffffffffu, sum, d);
                float m = sum * (1.0f / 128.0f);

                float dx = cx - m, dy = cy - m, dz = cz - m, dw = cw - m;
                float q = dx * dx + dy * dy + dz * dz + dw * dw;
                #pragma unroll
                for (int d = 16; d; d >>= 1) q += __shfl_xor_sync(0xffffffffu, q, d);
                float rr = rsqrtf(q * (1.0f / 128.0f) + 1e-5f);

                float4 g4 = ((const float4*)lngl)[lane];
                float4 b4 = ((const float4*)lnbl)[lane];
                float4 o;
                o.x = fmaxf(dx * rr * g4.x + b4.x, 0.f) + hv.x;
                o.y = fmaxf(dy * rr * g4.y + b4.y, 0.f) + hv.y;
                o.z = fmaxf(dz * rr * g4.z + b4.z, 0.f) + hv.z;
                o.w = fmaxf(dw * rr * g4.w + b4.w, 0.f) + hv.w;
                ((float4*)g_h)[(size_t)node * 32 + lane] = o;
            }
        }
        grid_sync();
    }

    // ================= P8: final LN + FC (warp/node) ========================
    {
        float* sWfc = (float*)s_pool;          // 2688 floats, fits
        for (int i = tid; i < HID * 21; i += NTHREADS) sWfc[i] = Wfc[i];
        __syncthreads();

        for (int node = gwarp; node < N; node += nwarp) {
            float4 hv = ((const float4*)g_h)[(size_t)node * 32 + lane];
            float sum = hv.x + hv.y + hv.z + hv.w;
            #pragma unroll
            for (int d = 16; d; d >>= 1) sum += __shfl_xor_sync(0xffffffffu, sum, d);
            float m = sum * (1.0f / 128.0f);

            float dx = hv.x - m, dy = hv.y - m, dz = hv.z - m, dw = hv.w - m;
            float q = dx * dx + dy * dy + dz * dz + dw * dw;
            #pragma unroll
            for (int d = 16; d; d >>= 1) q += __shfl_xor_sync(0xffffffffu, q, d);
            float rr = rsqrtf(q * (1.0f / 128.0f) + 1e-5f);

            float4 g4 = ((const float4*)lnog)[lane];
            float4 b4 = ((const float4*)lnob)[lane];
            float h0 = dx * rr * g4.x + b4.x;
            float h1 = dy * rr * g4.y + b4.y;
            float h2 = dz * rr * g4.z + b4.z;
            float h3 = dw * rr * g4.w + b4.w;

            const float* wp = sWfc + (lane * 4) * 21;
            #pragma unroll
            for (int cls = 0; cls < 21; cls++) {
                float p = h0 * wp[cls] + h1 * wp[21 + cls]
                        + h2 * wp[42 + cls] + h3 * wp[63 + cls];
                #pragma unroll
                for (int d = 16; d; d >>= 1) p += __shfl_xor_sync(0xffffffffu, p, d);
                if (lane == 0) out[(size_t)node * 21 + cls] = p + bfc[cls];
            }
        }
    }
}

// ------------------------------- launch ------------------------------------
extern "C" void kernel_launch(void* const* d_in, const int* in_sizes, int n_in,
                              void* d_out, int out_size) {
    const float* x     = (const float*)d_in[0];
    const int*   ei    = (const int*)  d_in[1];
    const float* dist  = (const float*)d_in[2];
    const float* Wn    = (const float*)d_in[3];
    const float* bn    = (const float*)d_in[4];
    const float* Wf    = (const float*)d_in[5];
    const float* bf    = (const float*)d_in[6];
    const float* Ws    = (const float*)d_in[7];
    const float* bs    = (const float*)d_in[8];
    const float* bng   = (const float*)d_in[9];
    const float* bnb   = (const float*)d_in[10];
    const float* lng   = (const float*)d_in[11];
    const float* lnb   = (const float*)d_in[12];
    const float* lnog  = (const float*)d_in[13];
    const float* lnob  = (const float*)d_in[14];
    const float* Wfc   = (const float*)d_in[15];
    const float* bfc   = (const float*)d_in[16];

    const int N = in_sizes[0] / 6;        // 20000
    const int E = in_sizes[2];            // 320000
    int L = in_sizes[6] / HID;            // 4
    if (L > LMAX) L = LMAX;

    mega_kernel<<<NBLOCKS, NTHREADS>>>(x, ei, dist, Wn, bn, Wf, bf, Ws, bs,
                                       bng, bnb, lng, lnb, lnog, lnob, Wfc, bfc,
                                       (float*)d_out, N, E, L);
}